// round 12
// baseline (speedup 1.0000x reference)
#include <cuda_runtime.h>
#include <stdint.h>

#define LQ 512
#define BQ 8
#define DQ 64
#define HQ 256
#define NROW 4096
#define GDIM 1024

typedef unsigned long long ull;

__device__ float g_attn [BQ*LQ*DQ];
__device__ float g_lines[3*NROW*DQ];
__device__ float g_xg   [3*NROW*GDIM];
__device__ float g_h0   [3*NROW*HQ];
__device__ float g_h1   [3*NROW*HQ];
__device__ float g_part [32*2*HQ];

static __device__ __forceinline__ float tanh_fast(float x) {
    float y; asm("tanh.approx.f32 %0, %1;" : "=f"(y) : "f"(x)); return y;
}
static __device__ __forceinline__ float sigmoid_e(float x) {
    return 1.f/(1.f + __expf(-x));
}
static __device__ __forceinline__ float tanh_e(float x) {
    return 1.f - 2.f/(__expf(2.f*x) + 1.f);
}
static __device__ __forceinline__ ull pack2(float lo, float hi) {
    ull r; asm("mov.b64 %0, {%1, %2};" : "=l"(r) : "f"(lo), "f"(hi)); return r;
}
static __device__ __forceinline__ void ffma2(ull& acc, ull w, ull h) {
    asm("fma.rn.f32x2 %0, %1, %2, %0;" : "+l"(acc) : "l"(w), "l"(h));
}
static __device__ __forceinline__ float pairsum(ull v) {
    float lo, hi; asm("mov.b64 {%0, %1}, %2;" : "=f"(lo), "=f"(hi) : "l"(v));
    return lo + hi;
}
static __device__ __forceinline__ uint32_t smem_u32(const void* p) {
    uint32_t a;
    asm("{ .reg .u64 t; cvta.to.shared.u64 t, %1; cvt.u32.u64 %0, t; }" : "=r"(a) : "l"(p));
    return a;
}
static __device__ __forceinline__ float blockSum(float v, float* red, int nw) {
    #pragma unroll
    for (int o = 16; o; o >>= 1) v += __shfl_xor_sync(0xffffffffu, v, o);
    if ((threadIdx.x & 31) == 0) red[threadIdx.x >> 5] = v;
    __syncthreads();
    float r = red[0];
    for (int i = 1; i < nw; i++) r += red[i];
    __syncthreads();
    return r;
}
static __device__ __forceinline__ float blockMax(float v, float* red, int nw) {
    #pragma unroll
    for (int o = 16; o; o >>= 1) v = fmaxf(v, __shfl_xor_sync(0xffffffffu, v, o));
    if ((threadIdx.x & 31) == 0) red[threadIdx.x >> 5] = v;
    __syncthreads();
    float r = red[0];
    for (int i = 1; i < nw; i++) r = fmaxf(r, red[i]);
    __syncthreads();
    return r;
}

__global__ __launch_bounds__(128) void attn_kernel(const float* __restrict__ x,
                                                   const float* __restrict__ attn_w)
{
    __shared__ float xl[DQ];
    __shared__ float s1[LQ], s2[LQ], p1[LQ], p2[LQ];
    __shared__ float red[4];
    __shared__ float comb[3][DQ];
    const int l = blockIdx.x, b = blockIdx.y, tid = threadIdx.x;
    const float* xb = x + (size_t)b * LQ * DQ;

    if (tid < DQ) xl[tid] = xb[(size_t)l * DQ + tid];
    __syncthreads();

    for (int m = tid; m <= l; m += 128) {
        const float4* row = (const float4*)(xb + (size_t)m * DQ);
        float dot = 0.f, ts = 0.f;
        #pragma unroll
        for (int q = 0; q < 16; q++) {
            float4 v = row[q];
            float a0 = xl[4*q+0], a1 = xl[4*q+1], a2 = xl[4*q+2], a3 = xl[4*q+3];
            dot += a0*v.x + a1*v.y + a2*v.z + a3*v.w;
            ts  += tanh_fast(a0+v.x) + tanh_fast(a1+v.y)
                 + tanh_fast(a2+v.z) + tanh_fast(a3+v.w);
        }
        s1[m] = dot; s2[m] = ts;
    }
    __syncthreads();

    float m1 = -1e30f, m3 = -1e30f;
    for (int m = tid; m <= l; m += 128) { m1 = fmaxf(m1, s1[m]); m3 = fmaxf(m3, s2[m]); }
    m1 = blockMax(m1, red, 4);
    m3 = blockMax(m3, red, 4);
    float m2 = m1 * 0.125f;

    float z1 = 0.f, z2 = 0.f, z3 = 0.f;
    for (int m = tid; m <= l; m += 128) {
        float e1 = __expf(s1[m] - m1);
        float e2 = __expf(s1[m]*0.125f - m2);
        float e3 = __expf(s2[m] - m3);
        p1[m] = e1; p2[m] = e2; s2[m] = e3;
        z1 += e1; z2 += e2; z3 += e3;
    }
    z1 = blockSum(z1, red, 4);
    z2 = blockSum(z2, red, 4);
    z3 = blockSum(z3, red, 4);
    const float i1 = 1.f/z1, i2 = 1.f/z2, i3 = 1.f/z3;

    const int d = tid & 63, half = tid >> 6;
    float aP = 0.f, aS = 0.f, aA = 0.f;
    for (int m = half; m <= l; m += 2) {
        float xv = xb[(size_t)m * DQ + d];
        aP += p1[m]*xv; aS += p2[m]*xv; aA += s2[m]*xv;
    }
    if (half) { comb[0][d] = aP; comb[1][d] = aS; comb[2][d] = aA; }
    __syncthreads();
    if (!half) {
        aP = (aP + comb[0][d]) * i1;
        aS = (aS + comb[1][d]) * i2;
        aA = (aA + comb[2][d]) * i3;
        float w0 = attn_w[(size_t)(0*LQ + l)*DQ + d];
        float w1 = attn_w[(size_t)(1*LQ + l)*DQ + d];
        float w2 = attn_w[(size_t)(2*LQ + l)*DQ + d];
        float inv = 1.f/(w0 + w1 + w2);
        g_attn[((size_t)b*LQ + l)*DQ + d] = (aP*w0 + aA*w1 + aS*w2)*inv;
    }
}

__global__ __launch_bounds__(256) void bn1_kernel(const float* __restrict__ src,
                                                  const float* __restrict__ gamma,
                                                  const float* __restrict__ beta)
{
    __shared__ float vals[NROW];
    __shared__ float red[8];
    const int d = blockIdx.x, line = blockIdx.y, tid = threadIdx.x;
    float s = 0.f, ss = 0.f;
    for (int idx = tid; idx < NROW; idx += 256) {
        size_t off = (size_t)idx * DQ + d;
        float v;
        if (line == 0)      v = src[off];
        else if (line == 1) v = src[off] + g_attn[off];
        else                v = g_attn[off];
        vals[idx] = v; s += v; ss += v*v;
    }
    s  = blockSum(s,  red, 8);
    ss = blockSum(ss, red, 8);
    float mu  = s * (1.f/NROW);
    float var = ss * (1.f/NROW) - mu*mu;
    float scale = gamma[line*DQ + d] * rsqrtf(var + 1e-5f);
    float shift = beta [line*DQ + d] - mu*scale;
    float* dst = g_lines + (size_t)line * NROW * DQ;
    for (int idx = tid; idx < NROW; idx += 256) {
        int bb = idx >> 9, ll = idx & 511;
        dst[(size_t)(ll*8 + bb)*DQ + d] = vals[idx]*scale + shift;
    }
}

__global__ __launch_bounds__(256) void gemm_kernel(const float* __restrict__ W,
                                                   const float* __restrict__ bias1,
                                                   const float* __restrict__ bias2,
                                                   int K, int phase)
{
    __shared__ float As[16][68];
    __shared__ float Bs[16][68];
    const int stack = blockIdx.z;
    const float* Ab = (phase ? g_h0 : g_lines) + (size_t)stack * NROW * K;
    const float* Wb = W + (size_t)stack * GDIM * K;
    const float* b1 = bias1 + stack * GDIM;
    const float* b2 = bias2 + stack * GDIM;
    float* Cb = g_xg + (size_t)stack * NROW * GDIM;
    const int m0 = blockIdx.x * 64, n0 = blockIdx.y * 64;
    const int tid = threadIdx.x;
    const int tm = tid & 15, tn = tid >> 4;
    const int li = tid >> 2, lj = tid & 3;
    float acc[4][4] = {};
    for (int k0 = 0; k0 < K; k0 += 16) {
        float4 av = *(const float4*)&Ab[(size_t)(m0+li)*K + k0 + lj*4];
        float4 wv = *(const float4*)&Wb[(size_t)(n0+li)*K + k0 + lj*4];
        As[lj*4+0][li] = av.x; As[lj*4+1][li] = av.y; As[lj*4+2][li] = av.z; As[lj*4+3][li] = av.w;
        Bs[lj*4+0][li] = wv.x; Bs[lj*4+1][li] = wv.y; Bs[lj*4+2][li] = wv.z; Bs[lj*4+3][li] = wv.w;
        __syncthreads();
        #pragma unroll
        for (int kk = 0; kk < 16; kk++) {
            float4 a  = *(const float4*)&As[kk][tm*4];
            float4 w4 = *(const float4*)&Bs[kk][tn*4];
            float ar[4] = {a.x, a.y, a.z, a.w};
            float wr[4] = {w4.x, w4.y, w4.z, w4.w};
            #pragma unroll
            for (int i2 = 0; i2 < 4; i2++)
                #pragma unroll
                for (int j2 = 0; j2 < 4; j2++)
                    acc[i2][j2] = fmaf(ar[i2], wr[j2], acc[i2][j2]);
        }
        __syncthreads();
    }
    #pragma unroll
    for (int j2 = 0; j2 < 4; j2++) {
        int n = n0 + tn*4 + j2;
        float bsum = b1[n] + b2[n];
        #pragma unroll
        for (int i2 = 0; i2 < 4; i2++) {
            int m = m0 + tm*4 + i2;
            Cb[(size_t)m*GDIM + n] = acc[i2][j2] + bsum;
        }
    }
}

// ---- LSTM: cluster of 8 CTAs; paired DSMEM h-broadcast + split HW cluster barrier ----
#define SEG 68
__global__ __launch_bounds__(512, 1) void lstm_kernel(const float* __restrict__ Whh,
                                                      int phase)
{
    const int ug = blockIdx.x, bg = blockIdx.y, stack = blockIdx.z;
    const int tid = threadIdx.x;
    const int r = tid >> 2, kq = tid & 3;
    const int gi = r >> 5, u = r & 31;
    const int j0 = ug * 32;

    __shared__ __align__(16) float hs[2][2][4*SEG];   // [parity][batch][seg]
    __shared__ float sgate[128][2];

    ull wp[32];
    {
        const float* wrow = Whh + ((size_t)stack << 18)
                          + ((size_t)(gi*256 + j0 + u) << 8) + kq*64;
        #pragma unroll
        for (int i = 0; i < 32; i++) wp[i] = pack2(wrow[2*i], wrow[2*i+1]);
    }
    for (int i = tid; i < 2*2*4*SEG; i += 512) ((float*)hs)[i] = 0.f;

    const float* xg_s = g_xg + (size_t)stack * NROW * GDIM;
    float* hseq_s = (phase ? g_h1 : g_h0) + (size_t)stack * NROW * HQ;

    const int au = tid >> 1, ab = tid & 1;
    const int bglob = bg*2 + ab;
    float c_state = 0.f;

    float xr0 = 0.f, xr1 = 0.f, xr2 = 0.f, xr3 = 0.f;
    if (tid < 64) {
        const float* xp = xg_s + (size_t)(0*8 + bglob)*GDIM + j0 + au;
        xr0 = xp[0]; xr1 = xp[256]; xr2 = xp[512]; xr3 = xp[768];
    }
    asm volatile("barrier.cluster.arrive.aligned;" ::: "memory");
    asm volatile("barrier.cluster.wait.aligned;" ::: "memory");

    for (int t = 0; t < LQ; t++) {
        const int par = t & 1;
        const ulonglong2* h0 = (const ulonglong2*)&hs[par][0][kq*SEG];
        const ulonglong2* h1 = (const ulonglong2*)&hs[par][1][kq*SEG];
        // dual accumulators per batch: 4-way ILP
        ull a0a = pack2(0.f, 0.f), a0b = pack2(0.f, 0.f);
        ull a1a = pack2(0.f, 0.f), a1b = pack2(0.f, 0.f);
        #pragma unroll
        for (int i = 0; i < 16; i++) {
            ulonglong2 v0 = h0[i], v1 = h1[i];
            ffma2(a0a, wp[2*i],   v0.x);
            ffma2(a0b, wp[2*i+1], v0.y);
            ffma2(a1a, wp[2*i],   v1.x);
            ffma2(a1b, wp[2*i+1], v1.y);
        }
        float d0 = pairsum(a0a) + pairsum(a0b);
        float d1 = pairsum(a1a) + pairsum(a1b);
        d0 += __shfl_xor_sync(0xffffffffu, d0, 1);
        d1 += __shfl_xor_sync(0xffffffffu, d1, 1);
        d0 += __shfl_xor_sync(0xffffffffu, d0, 2);
        d1 += __shfl_xor_sync(0xffffffffu, d1, 2);
        if (kq == 0) { sgate[r][0] = d0; sgate[r][1] = d1; }
        __syncthreads();   // all hs[par] reads complete before any arrive below

        if (tid < 64) {
            float pi = sgate[ 0 + au][ab] + xr0;
            float pf = sgate[32 + au][ab] + xr1;
            float pg = sgate[64 + au][ab] + xr2;
            float po = sgate[96 + au][ab] + xr3;
            float ig = sigmoid_e(pi);
            float fg = sigmoid_e(pf);
            float gg = tanh_e(pg);
            float og = sigmoid_e(po);
            float c  = fg * c_state + ig * gg;
            c_state = c;
            float h = og * tanh_e(c);
            const int k = j0 + au;
            // pair adjacent-k producers (same batch): tid and tid^2
            float hnb = __shfl_xor_sync(0xffffffffu, h, 2);
            if ((au & 1) == 0) {
                ull hv2 = pack2(h, hnb);   // {h_k, h_k+1}, k even
                uint32_t laddr = smem_u32(&hs[par^1][ab][(k >> 6)*SEG + (k & 63)]);
                #pragma unroll
                for (int tgt = 0; tgt < 8; tgt++) {
                    uint32_t raddr;
                    asm volatile("mapa.shared::cluster.u32 %0, %1, %2;"
                                 : "=r"(raddr) : "r"(laddr), "r"(tgt));
                    asm volatile("st.shared::cluster.b64 [%0], %1;"
                                 :: "r"(raddr), "l"(hv2) : "memory");
                }
            }
            // producer arrive: release publishes the remote stores
            asm volatile("barrier.cluster.arrive.aligned;" ::: "memory");
            // overlap gmem traffic with barrier latency
            hseq_s[(size_t)(t*8 + bglob)*HQ + k] = h;
            if (t + 1 < LQ) {
                const float* xp = xg_s + (size_t)((t+1)*8 + bglob)*GDIM + j0 + au;
                xr0 = xp[0]; xr1 = xp[256]; xr2 = xp[512]; xr3 = xp[768];
            }
        } else {
            // non-producers: nothing to publish -> relaxed arrive
            asm volatile("barrier.cluster.arrive.relaxed.aligned;" ::: "memory");
        }
        asm volatile("barrier.cluster.wait.aligned;" ::: "memory");
    }
}

__global__ __launch_bounds__(256) void bn2stats_kernel(const float* __restrict__ cat_w)
{
    const int h = threadIdx.x, blk = blockIdx.x;
    float s = 0.f, ss = 0.f;
    for (int tt = 0; tt < 16; tt++) {
        int t = blk*16 + tt;
        float w0 = cat_w[(size_t)(0*LQ + t)*HQ + h];
        float w1 = cat_w[(size_t)(1*LQ + t)*HQ + h];
        float w2 = cat_w[(size_t)(2*LQ + t)*HQ + h];
        float inv = 1.f/(w0 + w1 + w2);
        w0 *= inv; w1 *= inv; w2 *= inv;
        #pragma unroll
        for (int b = 0; b < 8; b++) {
            size_t row = (size_t)(t*8 + b)*HQ + h;
            float v = g_h1[row]*w0 + g_h1[row + (size_t)NROW*HQ]*w1
                    + g_h1[row + 2*(size_t)NROW*HQ]*w2;
            s += v; ss += v*v;
        }
    }
    g_part[(blk*2 + 0)*HQ + h] = s;
    g_part[(blk*2 + 1)*HQ + h] = ss;
}

__global__ __launch_bounds__(256) void final_kernel(const float* __restrict__ cat_w,
                                                    const float* __restrict__ g2,
                                                    const float* __restrict__ b2,
                                                    const float* __restrict__ fcW,
                                                    const float* __restrict__ fcb,
                                                    float* __restrict__ out)
{
    __shared__ float catn[HQ][BQ];
    const int tid = threadIdx.x;
    float s = 0.f, ss = 0.f;
    for (int blk = 0; blk < 32; blk++) {
        s  += g_part[(blk*2 + 0)*HQ + tid];
        ss += g_part[(blk*2 + 1)*HQ + tid];
    }
    float mu  = s * (1.f/NROW);
    float var = ss * (1.f/NROW) - mu*mu;
    float scale = g2[tid] * rsqrtf(var + 1e-5f);
    float shift = b2[tid] - mu*scale;

    const int t = LQ - 1;
    float w0 = cat_w[(size_t)(0*LQ + t)*HQ + tid];
    float w1 = cat_w[(size_t)(1*LQ + t)*HQ + tid];
    float w2 = cat_w[(size_t)(2*LQ + t)*HQ + tid];
    float inv = 1.f/(w0 + w1 + w2);
    w0 *= inv; w1 *= inv; w2 *= inv;
    #pragma unroll
    for (int b = 0; b < 8; b++) {
        size_t row = (size_t)(t*8 + b)*HQ + tid;
        float v = g_h1[row]*w0 + g_h1[row + (size_t)NROW*HQ]*w1
                + g_h1[row + 2*(size_t)NROW*HQ]*w2;
        catn[tid][b] = v*scale + shift;
    }
    __syncthreads();
    if (tid < 64) {
        int b = tid >> 3, c = tid & 7;
        float acc = fcb[c];
        for (int hh = 0; hh < HQ; hh++) acc = fmaf(catn[hh][b], fcW[c*HQ + hh], acc);
        out[b*8 + c] = acc;
    }
}

static void launch_lstm(const float* Whh, int phase, cudaStream_t st = 0)
{
    cudaLaunchConfig_t cfg = {};
    cfg.gridDim  = dim3(8, 4, 3);
    cfg.blockDim = dim3(512, 1, 1);
    cfg.dynamicSmemBytes = 0;
    cfg.stream = st;
    cudaLaunchAttribute attrs[1];
    attrs[0].id = cudaLaunchAttributeClusterDimension;
    attrs[0].val.clusterDim = {8, 1, 1};
    cfg.attrs = attrs;
    cfg.numAttrs = 1;
    cudaLaunchKernelEx(&cfg, lstm_kernel, Whh, phase);
}

extern "C" void kernel_launch(void* const* d_in, const int* in_sizes, int n_in,
                              void* d_out, int out_size)
{
    const float* src    = (const float*)d_in[0];
    const float* attn_w = (const float*)d_in[1];
    const float* cat_w  = (const float*)d_in[2];
    const float* bn1_g  = (const float*)d_in[3];
    const float* bn1_b  = (const float*)d_in[4];
    const float* bn2_g  = (const float*)d_in[5];
    const float* bn2_b  = (const float*)d_in[6];
    const float* Wih0   = (const float*)d_in[7];
    const float* Whh0   = (const float*)d_in[8];
    const float* bih0   = (const float*)d_in[9];
    const float* bhh0   = (const float*)d_in[10];
    const float* Wih1   = (const float*)d_in[11];
    const float* Whh1   = (const float*)d_in[12];
    const float* bih1   = (const float*)d_in[13];
    const float* bhh1   = (const float*)d_in[14];
    const float* fcW    = (const float*)d_in[15];
    const float* fcb    = (const float*)d_in[16];
    float* out = (float*)d_out;

    attn_kernel<<<dim3(LQ, BQ), 128>>>(src, attn_w);                  // 0
    bn1_kernel<<<dim3(DQ, 3), 256>>>(src, bn1_g, bn1_b);              // 1
    gemm_kernel<<<dim3(64, 16, 3), 256>>>(Wih0, bih0, bhh0, 64, 0);   // 2
    launch_lstm(Whh0, 0);                                             // 3
    gemm_kernel<<<dim3(64, 16, 3), 256>>>(Wih1, bih1, bhh1, 256, 1);  // 4
    launch_lstm(Whh1, 1);                                             // 5  <- ncu capture slot
    bn2stats_kernel<<<32, 256>>>(cat_w);                              // 6
    final_kernel<<<1, 256>>>(cat_w, bn2_g, bn2_b, fcW, fcb, out);     // 7
}

// round 13
// speedup vs baseline: 1.0027x; 1.0027x over previous
#include <cuda_runtime.h>
#include <stdint.h>

#define LQ 512
#define BQ 8
#define DQ 64
#define HQ 256
#define NROW 4096
#define GDIM 1024

typedef unsigned long long ull;

__device__ float g_attn [BQ*LQ*DQ];
__device__ float g_lines[3*NROW*DQ];
__device__ float g_xg   [3*NROW*GDIM];
__device__ float g_h0   [3*NROW*HQ];
__device__ float g_h1   [3*NROW*HQ];
__device__ float g_part [32*2*HQ];

static __device__ __forceinline__ float tanh_fast(float x) {
    float y; asm("tanh.approx.f32 %0, %1;" : "=f"(y) : "f"(x)); return y;
}
static __device__ __forceinline__ float sigmoid_e(float x) {
    return 1.f/(1.f + __expf(-x));
}
static __device__ __forceinline__ float tanh_e(float x) {
    return 1.f - 2.f/(__expf(2.f*x) + 1.f);
}
static __device__ __forceinline__ ull pack2(float lo, float hi) {
    ull r; asm("mov.b64 %0, {%1, %2};" : "=l"(r) : "f"(lo), "f"(hi)); return r;
}
static __device__ __forceinline__ void ffma2(ull& acc, ull w, ull h) {
    asm("fma.rn.f32x2 %0, %1, %2, %0;" : "+l"(acc) : "l"(w), "l"(h));
}
static __device__ __forceinline__ float pairsum(ull v) {
    float lo, hi; asm("mov.b64 {%0, %1}, %2;" : "=f"(lo), "=f"(hi) : "l"(v));
    return lo + hi;
}
static __device__ __forceinline__ uint32_t smem_u32(const void* p) {
    uint32_t a;
    asm("{ .reg .u64 t; cvta.to.shared.u64 t, %1; cvt.u32.u64 %0, t; }" : "=r"(a) : "l"(p));
    return a;
}
static __device__ __forceinline__ float blockSum(float v, float* red, int nw) {
    #pragma unroll
    for (int o = 16; o; o >>= 1) v += __shfl_xor_sync(0xffffffffu, v, o);
    if ((threadIdx.x & 31) == 0) red[threadIdx.x >> 5] = v;
    __syncthreads();
    float r = red[0];
    for (int i = 1; i < nw; i++) r += red[i];
    __syncthreads();
    return r;
}
static __device__ __forceinline__ float blockMax(float v, float* red, int nw) {
    #pragma unroll
    for (int o = 16; o; o >>= 1) v = fmaxf(v, __shfl_xor_sync(0xffffffffu, v, o));
    if ((threadIdx.x & 31) == 0) red[threadIdx.x >> 5] = v;
    __syncthreads();
    float r = red[0];
    for (int i = 1; i < nw; i++) r = fmaxf(r, red[i]);
    __syncthreads();
    return r;
}

__global__ __launch_bounds__(128) void attn_kernel(const float* __restrict__ x,
                                                   const float* __restrict__ attn_w)
{
    __shared__ float xl[DQ];
    __shared__ float s1[LQ], s2[LQ], p1[LQ], p2[LQ];
    __shared__ float red[4];
    __shared__ float comb[3][DQ];
    const int l = blockIdx.x, b = blockIdx.y, tid = threadIdx.x;
    const float* xb = x + (size_t)b * LQ * DQ;

    if (tid < DQ) xl[tid] = xb[(size_t)l * DQ + tid];
    __syncthreads();

    for (int m = tid; m <= l; m += 128) {
        const float4* row = (const float4*)(xb + (size_t)m * DQ);
        float dot = 0.f, ts = 0.f;
        #pragma unroll
        for (int q = 0; q < 16; q++) {
            float4 v = row[q];
            float a0 = xl[4*q+0], a1 = xl[4*q+1], a2 = xl[4*q+2], a3 = xl[4*q+3];
            dot += a0*v.x + a1*v.y + a2*v.z + a3*v.w;
            ts  += tanh_fast(a0+v.x) + tanh_fast(a1+v.y)
                 + tanh_fast(a2+v.z) + tanh_fast(a3+v.w);
        }
        s1[m] = dot; s2[m] = ts;
    }
    __syncthreads();

    float m1 = -1e30f, m3 = -1e30f;
    for (int m = tid; m <= l; m += 128) { m1 = fmaxf(m1, s1[m]); m3 = fmaxf(m3, s2[m]); }
    m1 = blockMax(m1, red, 4);
    m3 = blockMax(m3, red, 4);
    float m2 = m1 * 0.125f;

    float z1 = 0.f, z2 = 0.f, z3 = 0.f;
    for (int m = tid; m <= l; m += 128) {
        float e1 = __expf(s1[m] - m1);
        float e2 = __expf(s1[m]*0.125f - m2);
        float e3 = __expf(s2[m] - m3);
        p1[m] = e1; p2[m] = e2; s2[m] = e3;
        z1 += e1; z2 += e2; z3 += e3;
    }
    z1 = blockSum(z1, red, 4);
    z2 = blockSum(z2, red, 4);
    z3 = blockSum(z3, red, 4);
    const float i1 = 1.f/z1, i2 = 1.f/z2, i3 = 1.f/z3;

    const int d = tid & 63, half = tid >> 6;
    float aP = 0.f, aS = 0.f, aA = 0.f;
    for (int m = half; m <= l; m += 2) {
        float xv = xb[(size_t)m * DQ + d];
        aP += p1[m]*xv; aS += p2[m]*xv; aA += s2[m]*xv;
    }
    if (half) { comb[0][d] = aP; comb[1][d] = aS; comb[2][d] = aA; }
    __syncthreads();
    if (!half) {
        aP = (aP + comb[0][d]) * i1;
        aS = (aS + comb[1][d]) * i2;
        aA = (aA + comb[2][d]) * i3;
        float w0 = attn_w[(size_t)(0*LQ + l)*DQ + d];
        float w1 = attn_w[(size_t)(1*LQ + l)*DQ + d];
        float w2 = attn_w[(size_t)(2*LQ + l)*DQ + d];
        float inv = 1.f/(w0 + w1 + w2);
        g_attn[((size_t)b*LQ + l)*DQ + d] = (aP*w0 + aA*w1 + aS*w2)*inv;
    }
}

__global__ __launch_bounds__(256) void bn1_kernel(const float* __restrict__ src,
                                                  const float* __restrict__ gamma,
                                                  const float* __restrict__ beta)
{
    __shared__ float vals[NROW];
    __shared__ float red[8];
    const int d = blockIdx.x, line = blockIdx.y, tid = threadIdx.x;
    float s = 0.f, ss = 0.f;
    for (int idx = tid; idx < NROW; idx += 256) {
        size_t off = (size_t)idx * DQ + d;
        float v;
        if (line == 0)      v = src[off];
        else if (line == 1) v = src[off] + g_attn[off];
        else                v = g_attn[off];
        vals[idx] = v; s += v; ss += v*v;
    }
    s  = blockSum(s,  red, 8);
    ss = blockSum(ss, red, 8);
    float mu  = s * (1.f/NROW);
    float var = ss * (1.f/NROW) - mu*mu;
    float scale = gamma[line*DQ + d] * rsqrtf(var + 1e-5f);
    float shift = beta [line*DQ + d] - mu*scale;
    float* dst = g_lines + (size_t)line * NROW * DQ;
    for (int idx = tid; idx < NROW; idx += 256) {
        int bb = idx >> 9, ll = idx & 511;
        dst[(size_t)(ll*8 + bb)*DQ + d] = vals[idx]*scale + shift;
    }
}

// ---- GEMM (f32x2): C[row][n] = A[row][:]·W[n][:] + b1[n] + b2[n] ----
// 128x128 tile, 512 threads, 4m x 8n per thread, k-pairs packed as float2.
__global__ __launch_bounds__(512) void gemm_kernel(const float* __restrict__ W,
                                                   const float* __restrict__ bias1,
                                                   const float* __restrict__ bias2,
                                                   int K, int phase)
{
    __shared__ float2 As2[8][130];
    __shared__ float2 Bs2[8][130];
    const int stack = blockIdx.z;
    const float* Ab = (phase ? g_h0 : g_lines) + (size_t)stack * NROW * K;
    const float* Wb = W + (size_t)stack * GDIM * K;
    const float* b1 = bias1 + stack * GDIM;
    const float* b2 = bias2 + stack * GDIM;
    float* Cb = g_xg + (size_t)stack * NROW * GDIM;
    const int m0 = blockIdx.x * 128, n0 = blockIdx.y * 128;
    const int tid = threadIdx.x;
    const int tm = tid & 31;          // m-group (4 rows)
    const int tn = tid >> 5;          // n-group (8 cols) — uniform per warp -> B broadcast
    const int lr = tid >> 2, lf = tid & 3;

    ull acc[4][8];
    #pragma unroll
    for (int i = 0; i < 4; i++)
        #pragma unroll
        for (int j = 0; j < 8; j++) acc[i][j] = pack2(0.f, 0.f);

    for (int k0 = 0; k0 < K; k0 += 16) {
        float4 av = *(const float4*)&Ab[(size_t)(m0+lr)*K + k0 + lf*4];
        float4 wv = *(const float4*)&Wb[(size_t)(n0+lr)*K + k0 + lf*4];
        As2[lf*2  ][lr] = make_float2(av.x, av.y);
        As2[lf*2+1][lr] = make_float2(av.z, av.w);
        Bs2[lf*2  ][lr] = make_float2(wv.x, wv.y);
        Bs2[lf*2+1][lr] = make_float2(wv.z, wv.w);
        __syncthreads();
        #pragma unroll
        for (int kk2 = 0; kk2 < 8; kk2++) {
            ulonglong2 aA = *(const ulonglong2*)&As2[kk2][tm*4];
            ulonglong2 aB = *(const ulonglong2*)&As2[kk2][tm*4 + 2];
            ull am[4] = {aA.x, aA.y, aB.x, aB.y};
            ulonglong2 b0 = *(const ulonglong2*)&Bs2[kk2][tn*8];
            ulonglong2 b1v = *(const ulonglong2*)&Bs2[kk2][tn*8 + 2];
            ulonglong2 b2v = *(const ulonglong2*)&Bs2[kk2][tn*8 + 4];
            ulonglong2 b3v = *(const ulonglong2*)&Bs2[kk2][tn*8 + 6];
            ull bn[8] = {b0.x, b0.y, b1v.x, b1v.y, b2v.x, b2v.y, b3v.x, b3v.y};
            #pragma unroll
            for (int i = 0; i < 4; i++)
                #pragma unroll
                for (int j = 0; j < 8; j++)
                    ffma2(acc[i][j], am[i], bn[j]);
        }
        __syncthreads();
    }
    #pragma unroll
    for (int i = 0; i < 4; i++) {
        int m = m0 + tm*4 + i;
        #pragma unroll
        for (int j = 0; j < 8; j++) {
            int n = n0 + tn*8 + j;
            Cb[(size_t)m*GDIM + n] = pairsum(acc[i][j]) + b1[n] + b2[n];
        }
    }
}

// ---- LSTM: cluster of 8 CTAs; DSMEM h-broadcast + split HW cluster barrier (R11) ----
#define SEG 68
__global__ __launch_bounds__(512, 1) void lstm_kernel(const float* __restrict__ Whh,
                                                      int phase)
{
    const int ug = blockIdx.x, bg = blockIdx.y, stack = blockIdx.z;
    const int tid = threadIdx.x;
    const int r = tid >> 2, kq = tid & 3;
    const int gi = r >> 5, u = r & 31;
    const int j0 = ug * 32;

    __shared__ __align__(16) float hs[2][2][4*SEG];   // [parity][batch][seg]
    __shared__ float sgate[128][2];

    ull wp[32];
    {
        const float* wrow = Whh + ((size_t)stack << 18)
                          + ((size_t)(gi*256 + j0 + u) << 8) + kq*64;
        #pragma unroll
        for (int i = 0; i < 32; i++) wp[i] = pack2(wrow[2*i], wrow[2*i+1]);
    }
    for (int i = tid; i < 2*2*4*SEG; i += 512) ((float*)hs)[i] = 0.f;

    const float* xg_s = g_xg + (size_t)stack * NROW * GDIM;
    float* hseq_s = (phase ? g_h1 : g_h0) + (size_t)stack * NROW * HQ;

    const int au = tid >> 1, ab = tid & 1;
    const int bglob = bg*2 + ab;
    float c_state = 0.f;

    float xr0 = 0.f, xr1 = 0.f, xr2 = 0.f, xr3 = 0.f;
    if (tid < 64) {
        const float* xp = xg_s + (size_t)(0*8 + bglob)*GDIM + j0 + au;
        xr0 = xp[0]; xr1 = xp[256]; xr2 = xp[512]; xr3 = xp[768];
    }
    asm volatile("barrier.cluster.arrive.aligned;" ::: "memory");
    asm volatile("barrier.cluster.wait.aligned;" ::: "memory");

    for (int t = 0; t < LQ; t++) {
        const int par = t & 1;
        const ulonglong2* h0 = (const ulonglong2*)&hs[par][0][kq*SEG];
        const ulonglong2* h1 = (const ulonglong2*)&hs[par][1][kq*SEG];
        ull acc0 = pack2(0.f, 0.f), acc1 = pack2(0.f, 0.f);
        #pragma unroll
        for (int i = 0; i < 16; i++) {
            ulonglong2 v0 = h0[i], v1 = h1[i];
            ffma2(acc0, wp[2*i],   v0.x);
            ffma2(acc0, wp[2*i+1], v0.y);
            ffma2(acc1, wp[2*i],   v1.x);
            ffma2(acc1, wp[2*i+1], v1.y);
        }
        float d0 = pairsum(acc0), d1 = pairsum(acc1);
        d0 += __shfl_xor_sync(0xffffffffu, d0, 1);
        d1 += __shfl_xor_sync(0xffffffffu, d1, 1);
        d0 += __shfl_xor_sync(0xffffffffu, d0, 2);
        d1 += __shfl_xor_sync(0xffffffffu, d1, 2);
        if (kq == 0) { sgate[r][0] = d0; sgate[r][1] = d1; }
        __syncthreads();   // all hs[par] reads complete before any arrive below

        if (tid < 64) {
            float pi = sgate[ 0 + au][ab] + xr0;
            float pf = sgate[32 + au][ab] + xr1;
            float pg = sgate[64 + au][ab] + xr2;
            float po = sgate[96 + au][ab] + xr3;
            float ig = sigmoid_e(pi);
            float fg = sigmoid_e(pf);
            float gg = tanh_e(pg);
            float og = sigmoid_e(po);
            float c  = fg * c_state + ig * gg;
            c_state = c;
            float h = og * tanh_e(c);
            const int k = j0 + au;
            uint32_t laddr = smem_u32(&hs[par^1][ab][(k >> 6)*SEG + (k & 63)]);
            #pragma unroll
            for (int tgt = 0; tgt < 8; tgt++) {
                uint32_t raddr;
                asm volatile("mapa.shared::cluster.u32 %0, %1, %2;"
                             : "=r"(raddr) : "r"(laddr), "r"(tgt));
                asm volatile("st.shared::cluster.f32 [%0], %1;"
                             :: "r"(raddr), "f"(h) : "memory");
            }
        }
        // arrive (release: publishes producers' remote stores), then overlap
        // gmem traffic with the barrier latency, then wait (acquire).
        asm volatile("barrier.cluster.arrive.aligned;" ::: "memory");
        if (tid < 64) {
            hseq_s[(size_t)(t*8 + bglob)*HQ + (j0 + au)] =
                hs[par^1][ab][((j0 + au) >> 6)*SEG + ((j0 + au) & 63)];
            if (t + 1 < LQ) {
                const float* xp = xg_s + (size_t)((t+1)*8 + bglob)*GDIM + j0 + au;
                xr0 = xp[0]; xr1 = xp[256]; xr2 = xp[512]; xr3 = xp[768];
            }
        }
        asm volatile("barrier.cluster.wait.aligned;" ::: "memory");
    }
}

__global__ __launch_bounds__(256) void bn2stats_kernel(const float* __restrict__ cat_w)
{
    const int h = threadIdx.x, blk = blockIdx.x;
    float s = 0.f, ss = 0.f;
    for (int tt = 0; tt < 16; tt++) {
        int t = blk*16 + tt;
        float w0 = cat_w[(size_t)(0*LQ + t)*HQ + h];
        float w1 = cat_w[(size_t)(1*LQ + t)*HQ + h];
        float w2 = cat_w[(size_t)(2*LQ + t)*HQ + h];
        float inv = 1.f/(w0 + w1 + w2);
        w0 *= inv; w1 *= inv; w2 *= inv;
        #pragma unroll
        for (int b = 0; b < 8; b++) {
            size_t row = (size_t)(t*8 + b)*HQ + h;
            float v = g_h1[row]*w0 + g_h1[row + (size_t)NROW*HQ]*w1
                    + g_h1[row + 2*(size_t)NROW*HQ]*w2;
            s += v; ss += v*v;
        }
    }
    g_part[(blk*2 + 0)*HQ + h] = s;
    g_part[(blk*2 + 1)*HQ + h] = ss;
}

__global__ __launch_bounds__(256) void final_kernel(const float* __restrict__ cat_w,
                                                    const float* __restrict__ g2,
                                                    const float* __restrict__ b2,
                                                    const float* __restrict__ fcW,
                                                    const float* __restrict__ fcb,
                                                    float* __restrict__ out)
{
    __shared__ float catn[HQ][BQ];
    const int tid = threadIdx.x;
    float s = 0.f, ss = 0.f;
    for (int blk = 0; blk < 32; blk++) {
        s  += g_part[(blk*2 + 0)*HQ + tid];
        ss += g_part[(blk*2 + 1)*HQ + tid];
    }
    float mu  = s * (1.f/NROW);
    float var = ss * (1.f/NROW) - mu*mu;
    float scale = g2[tid] * rsqrtf(var + 1e-5f);
    float shift = b2[tid] - mu*scale;

    const int t = LQ - 1;
    float w0 = cat_w[(size_t)(0*LQ + t)*HQ + tid];
    float w1 = cat_w[(size_t)(1*LQ + t)*HQ + tid];
    float w2 = cat_w[(size_t)(2*LQ + t)*HQ + tid];
    float inv = 1.f/(w0 + w1 + w2);
    w0 *= inv; w1 *= inv; w2 *= inv;
    #pragma unroll
    for (int b = 0; b < 8; b++) {
        size_t row = (size_t)(t*8 + b)*HQ + tid;
        float v = g_h1[row]*w0 + g_h1[row + (size_t)NROW*HQ]*w1
                + g_h1[row + 2*(size_t)NROW*HQ]*w2;
        catn[tid][b] = v*scale + shift;
    }
    __syncthreads();
    if (tid < 64) {
        int b = tid >> 3, c = tid & 7;
        float acc = fcb[c];
        for (int hh = 0; hh < HQ; hh++) acc = fmaf(catn[hh][b], fcW[c*HQ + hh], acc);
        out[b*8 + c] = acc;
    }
}

static void launch_lstm(const float* Whh, int phase, cudaStream_t st = 0)
{
    cudaLaunchConfig_t cfg = {};
    cfg.gridDim  = dim3(8, 4, 3);
    cfg.blockDim = dim3(512, 1, 1);
    cfg.dynamicSmemBytes = 0;
    cfg.stream = st;
    cudaLaunchAttribute attrs[1];
    attrs[0].id = cudaLaunchAttributeClusterDimension;
    attrs[0].val.clusterDim = {8, 1, 1};
    cfg.attrs = attrs;
    cfg.numAttrs = 1;
    cudaLaunchKernelEx(&cfg, lstm_kernel, Whh, phase);
}

extern "C" void kernel_launch(void* const* d_in, const int* in_sizes, int n_in,
                              void* d_out, int out_size)
{
    const float* src    = (const float*)d_in[0];
    const float* attn_w = (const float*)d_in[1];
    const float* cat_w  = (const float*)d_in[2];
    const float* bn1_g  = (const float*)d_in[3];
    const float* bn1_b  = (const float*)d_in[4];
    const float* bn2_g  = (const float*)d_in[5];
    const float* bn2_b  = (const float*)d_in[6];
    const float* Wih0   = (const float*)d_in[7];
    const float* Whh0   = (const float*)d_in[8];
    const float* bih0   = (const float*)d_in[9];
    const float* bhh0   = (const float*)d_in[10];
    const float* Wih1   = (const float*)d_in[11];
    const float* Whh1   = (const float*)d_in[12];
    const float* bih1   = (const float*)d_in[13];
    const float* bhh1   = (const float*)d_in[14];
    const float* fcW    = (const float*)d_in[15];
    const float* fcb    = (const float*)d_in[16];
    float* out = (float*)d_out;

    attn_kernel<<<dim3(LQ, BQ), 128>>>(src, attn_w);                  // 0
    bn1_kernel<<<dim3(DQ, 3), 256>>>(src, bn1_g, bn1_b);              // 1
    gemm_kernel<<<dim3(32, 8, 3), 512>>>(Wih0, bih0, bhh0, 64, 0);    // 2
    launch_lstm(Whh0, 0);                                             // 3
    gemm_kernel<<<dim3(32, 8, 3), 512>>>(Wih1, bih1, bhh1, 256, 1);   // 4
    launch_lstm(Whh1, 1);                                             // 5  <- ncu capture slot
    bn2stats_kernel<<<32, 256>>>(cat_w);                              // 6
    final_kernel<<<1, 256>>>(cat_w, bn2_g, bn2_b, fcW, fcb, out);     // 7
}

// round 14
// speedup vs baseline: 1.1519x; 1.1488x over previous
#include <cuda_runtime.h>
#include <stdint.h>

#define LQ 512
#define BQ 8
#define DQ 64
#define HQ 256
#define NROW 4096
#define GDIM 1024

typedef unsigned long long ull;

__device__ float g_attn [BQ*LQ*DQ];
__device__ float g_lines[3*NROW*DQ];
__device__ float g_xg   [3*NROW*GDIM];
__device__ float g_h0   [3*NROW*HQ];
__device__ float g_h1   [3*NROW*HQ];
__device__ float g_part [32*2*HQ];

static __device__ __forceinline__ float tanh_fast(float x) {
    float y; asm("tanh.approx.f32 %0, %1;" : "=f"(y) : "f"(x)); return y;
}
static __device__ __forceinline__ float sigmoid_t(float x) {
    return fmaf(0.5f, tanh_fast(0.5f*x), 0.5f);
}
static __device__ __forceinline__ ull pack2(float lo, float hi) {
    ull r; asm("mov.b64 %0, {%1, %2};" : "=l"(r) : "f"(lo), "f"(hi)); return r;
}
static __device__ __forceinline__ void ffma2(ull& acc, ull w, ull h) {
    asm("fma.rn.f32x2 %0, %1, %2, %0;" : "+l"(acc) : "l"(w), "l"(h));
}
static __device__ __forceinline__ float pairsum(ull v) {
    float lo, hi; asm("mov.b64 {%0, %1}, %2;" : "=f"(lo), "=f"(hi) : "l"(v));
    return lo + hi;
}
static __device__ __forceinline__ uint32_t smem_u32(const void* p) {
    uint32_t a;
    asm("{ .reg .u64 t; cvta.to.shared.u64 t, %1; cvt.u32.u64 %0, t; }" : "=r"(a) : "l"(p));
    return a;
}
static __device__ __forceinline__ float blockSum(float v, float* red, int nw) {
    #pragma unroll
    for (int o = 16; o; o >>= 1) v += __shfl_xor_sync(0xffffffffu, v, o);
    if ((threadIdx.x & 31) == 0) red[threadIdx.x >> 5] = v;
    __syncthreads();
    float r = red[0];
    for (int i = 1; i < nw; i++) r += red[i];
    __syncthreads();
    return r;
}
static __device__ __forceinline__ float blockMax(float v, float* red, int nw) {
    #pragma unroll
    for (int o = 16; o; o >>= 1) v = fmaxf(v, __shfl_xor_sync(0xffffffffu, v, o));
    if ((threadIdx.x & 31) == 0) red[threadIdx.x >> 5] = v;
    __syncthreads();
    float r = red[0];
    for (int i = 1; i < nw; i++) r = fmaxf(r, red[i]);
    __syncthreads();
    return r;
}

__global__ __launch_bounds__(128) void attn_kernel(const float* __restrict__ x,
                                                   const float* __restrict__ attn_w)
{
    __shared__ float xl[DQ];
    __shared__ float s1[LQ], s2[LQ], p1[LQ], p2[LQ];
    __shared__ float red[4];
    __shared__ float comb[3][DQ];
    const int l = blockIdx.x, b = blockIdx.y, tid = threadIdx.x;
    const float* xb = x + (size_t)b * LQ * DQ;

    if (tid < DQ) xl[tid] = xb[(size_t)l * DQ + tid];
    __syncthreads();

    for (int m = tid; m <= l; m += 128) {
        const float4* row = (const float4*)(xb + (size_t)m * DQ);
        float dot = 0.f, ts = 0.f;
        #pragma unroll
        for (int q = 0; q < 16; q++) {
            float4 v = row[q];
            float a0 = xl[4*q+0], a1 = xl[4*q+1], a2 = xl[4*q+2], a3 = xl[4*q+3];
            dot += a0*v.x + a1*v.y + a2*v.z + a3*v.w;
            ts  += tanh_fast(a0+v.x) + tanh_fast(a1+v.y)
                 + tanh_fast(a2+v.z) + tanh_fast(a3+v.w);
        }
        s1[m] = dot; s2[m] = ts;
    }
    __syncthreads();

    float m1 = -1e30f, m3 = -1e30f;
    for (int m = tid; m <= l; m += 128) { m1 = fmaxf(m1, s1[m]); m3 = fmaxf(m3, s2[m]); }
    m1 = blockMax(m1, red, 4);
    m3 = blockMax(m3, red, 4);
    float m2 = m1 * 0.125f;

    float z1 = 0.f, z2 = 0.f, z3 = 0.f;
    for (int m = tid; m <= l; m += 128) {
        float e1 = __expf(s1[m] - m1);
        float e2 = __expf(s1[m]*0.125f - m2);
        float e3 = __expf(s2[m] - m3);
        p1[m] = e1; p2[m] = e2; s2[m] = e3;
        z1 += e1; z2 += e2; z3 += e3;
    }
    z1 = blockSum(z1, red, 4);
    z2 = blockSum(z2, red, 4);
    z3 = blockSum(z3, red, 4);
    const float i1 = 1.f/z1, i2 = 1.f/z2, i3 = 1.f/z3;

    const int d = tid & 63, half = tid >> 6;
    float aP = 0.f, aS = 0.f, aA = 0.f;
    for (int m = half; m <= l; m += 2) {
        float xv = xb[(size_t)m * DQ + d];
        aP += p1[m]*xv; aS += p2[m]*xv; aA += s2[m]*xv;
    }
    if (half) { comb[0][d] = aP; comb[1][d] = aS; comb[2][d] = aA; }
    __syncthreads();
    if (!half) {
        aP = (aP + comb[0][d]) * i1;
        aS = (aS + comb[1][d]) * i2;
        aA = (aA + comb[2][d]) * i3;
        float w0 = attn_w[(size_t)(0*LQ + l)*DQ + d];
        float w1 = attn_w[(size_t)(1*LQ + l)*DQ + d];
        float w2 = attn_w[(size_t)(2*LQ + l)*DQ + d];
        float inv = 1.f/(w0 + w1 + w2);
        g_attn[((size_t)b*LQ + l)*DQ + d] = (aP*w0 + aA*w1 + aS*w2)*inv;
    }
}

__global__ __launch_bounds__(256) void bn1_kernel(const float* __restrict__ src,
                                                  const float* __restrict__ gamma,
                                                  const float* __restrict__ beta)
{
    __shared__ float vals[NROW];
    __shared__ float red[8];
    const int d = blockIdx.x, line = blockIdx.y, tid = threadIdx.x;
    float s = 0.f, ss = 0.f;
    for (int idx = tid; idx < NROW; idx += 256) {
        size_t off = (size_t)idx * DQ + d;
        float v;
        if (line == 0)      v = src[off];
        else if (line == 1) v = src[off] + g_attn[off];
        else                v = g_attn[off];
        vals[idx] = v; s += v; ss += v*v;
    }
    s  = blockSum(s,  red, 8);
    ss = blockSum(ss, red, 8);
    float mu  = s * (1.f/NROW);
    float var = ss * (1.f/NROW) - mu*mu;
    float scale = gamma[line*DQ + d] * rsqrtf(var + 1e-5f);
    float shift = beta [line*DQ + d] - mu*scale;
    float* dst = g_lines + (size_t)line * NROW * DQ;
    for (int idx = tid; idx < NROW; idx += 256) {
        int bb = idx >> 9, ll = idx & 511;
        dst[(size_t)(ll*8 + bb)*DQ + d] = vals[idx]*scale + shift;
    }
}

// ---- GEMM (R11 version: 64x64 tile, 256 threads) ----
__global__ __launch_bounds__(256) void gemm_kernel(const float* __restrict__ W,
                                                   const float* __restrict__ bias1,
                                                   const float* __restrict__ bias2,
                                                   int K, int phase)
{
    __shared__ float As[16][68];
    __shared__ float Bs[16][68];
    const int stack = blockIdx.z;
    const float* Ab = (phase ? g_h0 : g_lines) + (size_t)stack * NROW * K;
    const float* Wb = W + (size_t)stack * GDIM * K;
    const float* b1 = bias1 + stack * GDIM;
    const float* b2 = bias2 + stack * GDIM;
    float* Cb = g_xg + (size_t)stack * NROW * GDIM;
    const int m0 = blockIdx.x * 64, n0 = blockIdx.y * 64;
    const int tid = threadIdx.x;
    const int tm = tid & 15, tn = tid >> 4;
    const int li = tid >> 2, lj = tid & 3;
    float acc[4][4] = {};
    for (int k0 = 0; k0 < K; k0 += 16) {
        float4 av = *(const float4*)&Ab[(size_t)(m0+li)*K + k0 + lj*4];
        float4 wv = *(const float4*)&Wb[(size_t)(n0+li)*K + k0 + lj*4];
        As[lj*4+0][li] = av.x; As[lj*4+1][li] = av.y; As[lj*4+2][li] = av.z; As[lj*4+3][li] = av.w;
        Bs[lj*4+0][li] = wv.x; Bs[lj*4+1][li] = wv.y; Bs[lj*4+2][li] = wv.z; Bs[lj*4+3][li] = wv.w;
        __syncthreads();
        #pragma unroll
        for (int kk = 0; kk < 16; kk++) {
            float4 a  = *(const float4*)&As[kk][tm*4];
            float4 w4 = *(const float4*)&Bs[kk][tn*4];
            float ar[4] = {a.x, a.y, a.z, a.w};
            float wr[4] = {w4.x, w4.y, w4.z, w4.w};
            #pragma unroll
            for (int i2 = 0; i2 < 4; i2++)
                #pragma unroll
                for (int j2 = 0; j2 < 4; j2++)
                    acc[i2][j2] = fmaf(ar[i2], wr[j2], acc[i2][j2]);
        }
        __syncthreads();
    }
    #pragma unroll
    for (int j2 = 0; j2 < 4; j2++) {
        int n = n0 + tn*4 + j2;
        float bsum = b1[n] + b2[n];
        #pragma unroll
        for (int i2 = 0; i2 < 4; i2++) {
            int m = m0 + tm*4 + i2;
            Cb[(size_t)m*GDIM + n] = acc[i2][j2] + bsum;
        }
    }
}

// ---- LSTM: cluster of 8 CTAs; DSMEM h-broadcast + split HW cluster barrier (R11) ----
#define SEG 68
__global__ __launch_bounds__(512, 1) void lstm_kernel(const float* __restrict__ Whh,
                                                      int phase)
{
    const int ug = blockIdx.x, bg = blockIdx.y, stack = blockIdx.z;
    const int tid = threadIdx.x;
    const int r = tid >> 2, kq = tid & 3;
    const int gi = r >> 5, u = r & 31;
    const int j0 = ug * 32;

    __shared__ __align__(16) float hs[2][2][4*SEG];   // [parity][batch][seg]
    __shared__ float sgate[128][2];

    ull wp[32];
    {
        const float* wrow = Whh + ((size_t)stack << 18)
                          + ((size_t)(gi*256 + j0 + u) << 8) + kq*64;
        #pragma unroll
        for (int i = 0; i < 32; i++) wp[i] = pack2(wrow[2*i], wrow[2*i+1]);
    }
    for (int i = tid; i < 2*2*4*SEG; i += 512) ((float*)hs)[i] = 0.f;

    const float* xg_s = g_xg + (size_t)stack * NROW * GDIM;
    float* hseq_s = (phase ? g_h1 : g_h0) + (size_t)stack * NROW * HQ;

    const int au = tid >> 1, ab = tid & 1;
    const int bglob = bg*2 + ab;
    float c_state = 0.f;

    float xr0 = 0.f, xr1 = 0.f, xr2 = 0.f, xr3 = 0.f;
    if (tid < 64) {
        const float* xp = xg_s + (size_t)(0*8 + bglob)*GDIM + j0 + au;
        xr0 = xp[0]; xr1 = xp[256]; xr2 = xp[512]; xr3 = xp[768];
    }
    asm volatile("barrier.cluster.arrive.aligned;" ::: "memory");
    asm volatile("barrier.cluster.wait.aligned;" ::: "memory");

    for (int t = 0; t < LQ; t++) {
        const int par = t & 1;
        const ulonglong2* h0 = (const ulonglong2*)&hs[par][0][kq*SEG];
        const ulonglong2* h1 = (const ulonglong2*)&hs[par][1][kq*SEG];
        ull acc0 = pack2(0.f, 0.f), acc1 = pack2(0.f, 0.f);
        #pragma unroll
        for (int i = 0; i < 16; i++) {
            ulonglong2 v0 = h0[i], v1 = h1[i];
            ffma2(acc0, wp[2*i],   v0.x);
            ffma2(acc0, wp[2*i+1], v0.y);
            ffma2(acc1, wp[2*i],   v1.x);
            ffma2(acc1, wp[2*i+1], v1.y);
        }
        float d0 = pairsum(acc0), d1 = pairsum(acc1);
        d0 += __shfl_xor_sync(0xffffffffu, d0, 1);
        d1 += __shfl_xor_sync(0xffffffffu, d1, 1);
        d0 += __shfl_xor_sync(0xffffffffu, d0, 2);
        d1 += __shfl_xor_sync(0xffffffffu, d1, 2);
        if (kq == 0) { sgate[r][0] = d0; sgate[r][1] = d1; }
        __syncthreads();   // all hs[par] reads complete before any arrive below

        if (tid < 64) {
            float pi = sgate[ 0 + au][ab] + xr0;
            float pf = sgate[32 + au][ab] + xr1;
            float pg = sgate[64 + au][ab] + xr2;
            float po = sgate[96 + au][ab] + xr3;
            float ig = sigmoid_t(pi);
            float fg = sigmoid_t(pf);
            float gg = tanh_fast(pg);
            float og = sigmoid_t(po);
            float c  = fg * c_state + ig * gg;
            c_state = c;
            float h = og * tanh_fast(c);
            const int k = j0 + au;
            uint32_t laddr = smem_u32(&hs[par^1][ab][(k >> 6)*SEG + (k & 63)]);
            #pragma unroll
            for (int tgt = 0; tgt < 8; tgt++) {
                uint32_t raddr;
                asm volatile("mapa.shared::cluster.u32 %0, %1, %2;"
                             : "=r"(raddr) : "r"(laddr), "r"(tgt));
                asm volatile("st.shared::cluster.f32 [%0], %1;"
                             :: "r"(raddr), "f"(h) : "memory");
            }
        }
        // arrive (release: publishes producers' remote stores), then overlap
        // gmem traffic with the barrier latency, then wait (acquire).
        asm volatile("barrier.cluster.arrive.aligned;" ::: "memory");
        if (tid < 64) {
            hseq_s[(size_t)(t*8 + bglob)*HQ + (j0 + au)] =
                hs[par^1][ab][((j0 + au) >> 6)*SEG + ((j0 + au) & 63)];
            if (t + 1 < LQ) {
                const float* xp = xg_s + (size_t)((t+1)*8 + bglob)*GDIM + j0 + au;
                xr0 = xp[0]; xr1 = xp[256]; xr2 = xp[512]; xr3 = xp[768];
            }
        }
        asm volatile("barrier.cluster.wait.aligned;" ::: "memory");
    }
}

__global__ __launch_bounds__(256) void bn2stats_kernel(const float* __restrict__ cat_w)
{
    const int h = threadIdx.x, blk = blockIdx.x;
    float s = 0.f, ss = 0.f;
    for (int tt = 0; tt < 16; tt++) {
        int t = blk*16 + tt;
        float w0 = cat_w[(size_t)(0*LQ + t)*HQ + h];
        float w1 = cat_w[(size_t)(1*LQ + t)*HQ + h];
        float w2 = cat_w[(size_t)(2*LQ + t)*HQ + h];
        float inv = 1.f/(w0 + w1 + w2);
        w0 *= inv; w1 *= inv; w2 *= inv;
        #pragma unroll
        for (int b = 0; b < 8; b++) {
            size_t row = (size_t)(t*8 + b)*HQ + h;
            float v = g_h1[row]*w0 + g_h1[row + (size_t)NROW*HQ]*w1
                    + g_h1[row + 2*(size_t)NROW*HQ]*w2;
            s += v; ss += v*v;
        }
    }
    g_part[(blk*2 + 0)*HQ + h] = s;
    g_part[(blk*2 + 1)*HQ + h] = ss;
}

__global__ __launch_bounds__(256) void final_kernel(const float* __restrict__ cat_w,
                                                    const float* __restrict__ g2,
                                                    const float* __restrict__ b2,
                                                    const float* __restrict__ fcW,
                                                    const float* __restrict__ fcb,
                                                    float* __restrict__ out)
{
    __shared__ float catn[HQ][BQ];
    const int tid = threadIdx.x;
    float s = 0.f, ss = 0.f;
    for (int blk = 0; blk < 32; blk++) {
        s  += g_part[(blk*2 + 0)*HQ + tid];
        ss += g_part[(blk*2 + 1)*HQ + tid];
    }
    float mu  = s * (1.f/NROW);
    float var = ss * (1.f/NROW) - mu*mu;
    float scale = g2[tid] * rsqrtf(var + 1e-5f);
    float shift = b2[tid] - mu*scale;

    const int t = LQ - 1;
    float w0 = cat_w[(size_t)(0*LQ + t)*HQ + tid];
    float w1 = cat_w[(size_t)(1*LQ + t)*HQ + tid];
    float w2 = cat_w[(size_t)(2*LQ + t)*HQ + tid];
    float inv = 1.f/(w0 + w1 + w2);
    w0 *= inv; w1 *= inv; w2 *= inv;
    #pragma unroll
    for (int b = 0; b < 8; b++) {
        size_t row = (size_t)(t*8 + b)*HQ + tid;
        float v = g_h1[row]*w0 + g_h1[row + (size_t)NROW*HQ]*w1
                + g_h1[row + 2*(size_t)NROW*HQ]*w2;
        catn[tid][b] = v*scale + shift;
    }
    __syncthreads();
    if (tid < 64) {
        int b = tid >> 3, c = tid & 7;
        float acc = fcb[c];
        for (int hh = 0; hh < HQ; hh++) acc = fmaf(catn[hh][b], fcW[c*HQ + hh], acc);
        out[b*8 + c] = acc;
    }
}

static void launch_lstm(const float* Whh, int phase, cudaStream_t st = 0)
{
    cudaLaunchConfig_t cfg = {};
    cfg.gridDim  = dim3(8, 4, 3);
    cfg.blockDim = dim3(512, 1, 1);
    cfg.dynamicSmemBytes = 0;
    cfg.stream = st;
    cudaLaunchAttribute attrs[1];
    attrs[0].id = cudaLaunchAttributeClusterDimension;
    attrs[0].val.clusterDim = {8, 1, 1};
    cfg.attrs = attrs;
    cfg.numAttrs = 1;
    cudaLaunchKernelEx(&cfg, lstm_kernel, Whh, phase);
}

extern "C" void kernel_launch(void* const* d_in, const int* in_sizes, int n_in,
                              void* d_out, int out_size)
{
    const float* src    = (const float*)d_in[0];
    const float* attn_w = (const float*)d_in[1];
    const float* cat_w  = (const float*)d_in[2];
    const float* bn1_g  = (const float*)d_in[3];
    const float* bn1_b  = (const float*)d_in[4];
    const float* bn2_g  = (const float*)d_in[5];
    const float* bn2_b  = (const float*)d_in[6];
    const float* Wih0   = (const float*)d_in[7];
    const float* Whh0   = (const float*)d_in[8];
    const float* bih0   = (const float*)d_in[9];
    const float* bhh0   = (const float*)d_in[10];
    const float* Wih1   = (const float*)d_in[11];
    const float* Whh1   = (const float*)d_in[12];
    const float* bih1   = (const float*)d_in[13];
    const float* bhh1   = (const float*)d_in[14];
    const float* fcW    = (const float*)d_in[15];
    const float* fcb    = (const float*)d_in[16];
    float* out = (float*)d_out;

    attn_kernel<<<dim3(LQ, BQ), 128>>>(src, attn_w);                  // 0
    bn1_kernel<<<dim3(DQ, 3), 256>>>(src, bn1_g, bn1_b);              // 1
    gemm_kernel<<<dim3(64, 16, 3), 256>>>(Wih0, bih0, bhh0, 64, 0);   // 2
    launch_lstm(Whh0, 0);                                             // 3
    gemm_kernel<<<dim3(64, 16, 3), 256>>>(Wih1, bih1, bhh1, 256, 1);  // 4
    launch_lstm(Whh1, 1);                                             // 5  <- ncu capture slot
    bn2stats_kernel<<<32, 256>>>(cat_w);                              // 6
    final_kernel<<<1, 256>>>(cat_w, bn2_g, bn2_b, fcW, fcb, out);     // 7
}

// round 15
// speedup vs baseline: 1.1582x; 1.0054x over previous
#include <cuda_runtime.h>
#include <stdint.h>

#define LQ 512
#define BQ 8
#define DQ 64
#define HQ 256
#define NROW 4096
#define GDIM 1024

typedef unsigned long long ull;

__device__ float g_attn [BQ*LQ*DQ];
__device__ float g_lines[3*NROW*DQ];
__device__ float g_xg   [3*NROW*GDIM];
__device__ float g_h0   [3*NROW*HQ];
__device__ float g_h1   [3*NROW*HQ];
__device__ float g_part [32*2*HQ];

static __device__ __forceinline__ float tanh_fast(float x) {
    float y; asm("tanh.approx.f32 %0, %1;" : "=f"(y) : "f"(x)); return y;
}
static __device__ __forceinline__ float sigmoid_t(float x) {
    return fmaf(0.5f, tanh_fast(0.5f*x), 0.5f);
}
static __device__ __forceinline__ ull pack2(float lo, float hi) {
    ull r; asm("mov.b64 %0, {%1, %2};" : "=l"(r) : "f"(lo), "f"(hi)); return r;
}
static __device__ __forceinline__ void ffma2(ull& acc, ull w, ull h) {
    asm("fma.rn.f32x2 %0, %1, %2, %0;" : "+l"(acc) : "l"(w), "l"(h));
}
static __device__ __forceinline__ float pairsum(ull v) {
    float lo, hi; asm("mov.b64 {%0, %1}, %2;" : "=f"(lo), "=f"(hi) : "l"(v));
    return lo + hi;
}
static __device__ __forceinline__ uint32_t smem_u32(const void* p) {
    uint32_t a;
    asm("{ .reg .u64 t; cvta.to.shared.u64 t, %1; cvt.u32.u64 %0, t; }" : "=r"(a) : "l"(p));
    return a;
}
static __device__ __forceinline__ float blockSum(float v, float* red, int nw) {
    #pragma unroll
    for (int o = 16; o; o >>= 1) v += __shfl_xor_sync(0xffffffffu, v, o);
    if ((threadIdx.x & 31) == 0) red[threadIdx.x >> 5] = v;
    __syncthreads();
    float r = red[0];
    for (int i = 1; i < nw; i++) r += red[i];
    __syncthreads();
    return r;
}
static __device__ __forceinline__ float blockMax(float v, float* red, int nw) {
    #pragma unroll
    for (int o = 16; o; o >>= 1) v = fmaxf(v, __shfl_xor_sync(0xffffffffu, v, o));
    if ((threadIdx.x & 31) == 0) red[threadIdx.x >> 5] = v;
    __syncthreads();
    float r = red[0];
    for (int i = 1; i < nw; i++) r = fmaxf(r, red[i]);
    __syncthreads();
    return r;
}

__global__ __launch_bounds__(128) void attn_kernel(const float* __restrict__ x,
                                                   const float* __restrict__ attn_w)
{
    __shared__ float xl[DQ];
    __shared__ float s1[LQ], s2[LQ], p1[LQ], p2[LQ];
    __shared__ float red[4];
    __shared__ float comb[3][DQ];
    const int l = blockIdx.x, b = blockIdx.y, tid = threadIdx.x;
    const float* xb = x + (size_t)b * LQ * DQ;

    if (tid < DQ) xl[tid] = xb[(size_t)l * DQ + tid];
    __syncthreads();

    for (int m = tid; m <= l; m += 128) {
        const float4* row = (const float4*)(xb + (size_t)m * DQ);
        float dot = 0.f, ts = 0.f;
        #pragma unroll
        for (int q = 0; q < 16; q++) {
            float4 v = row[q];
            float a0 = xl[4*q+0], a1 = xl[4*q+1], a2 = xl[4*q+2], a3 = xl[4*q+3];
            dot += a0*v.x + a1*v.y + a2*v.z + a3*v.w;
            ts  += tanh_fast(a0+v.x) + tanh_fast(a1+v.y)
                 + tanh_fast(a2+v.z) + tanh_fast(a3+v.w);
        }
        s1[m] = dot; s2[m] = ts;
    }
    __syncthreads();

    float m1 = -1e30f, m3 = -1e30f;
    for (int m = tid; m <= l; m += 128) { m1 = fmaxf(m1, s1[m]); m3 = fmaxf(m3, s2[m]); }
    m1 = blockMax(m1, red, 4);
    m3 = blockMax(m3, red, 4);
    float m2 = m1 * 0.125f;

    float z1 = 0.f, z2 = 0.f, z3 = 0.f;
    for (int m = tid; m <= l; m += 128) {
        float e1 = __expf(s1[m] - m1);
        float e2 = __expf(s1[m]*0.125f - m2);
        float e3 = __expf(s2[m] - m3);
        p1[m] = e1; p2[m] = e2; s2[m] = e3;
        z1 += e1; z2 += e2; z3 += e3;
    }
    z1 = blockSum(z1, red, 4);
    z2 = blockSum(z2, red, 4);
    z3 = blockSum(z3, red, 4);
    const float i1 = 1.f/z1, i2 = 1.f/z2, i3 = 1.f/z3;

    const int d = tid & 63, half = tid >> 6;
    float aP = 0.f, aS = 0.f, aA = 0.f;
    for (int m = half; m <= l; m += 2) {
        float xv = xb[(size_t)m * DQ + d];
        aP += p1[m]*xv; aS += p2[m]*xv; aA += s2[m]*xv;
    }
    if (half) { comb[0][d] = aP; comb[1][d] = aS; comb[2][d] = aA; }
    __syncthreads();
    if (!half) {
        aP = (aP + comb[0][d]) * i1;
        aS = (aS + comb[1][d]) * i2;
        aA = (aA + comb[2][d]) * i3;
        float w0 = attn_w[(size_t)(0*LQ + l)*DQ + d];
        float w1 = attn_w[(size_t)(1*LQ + l)*DQ + d];
        float w2 = attn_w[(size_t)(2*LQ + l)*DQ + d];
        float inv = 1.f/(w0 + w1 + w2);
        g_attn[((size_t)b*LQ + l)*DQ + d] = (aP*w0 + aA*w1 + aS*w2)*inv;
    }
}

__global__ __launch_bounds__(256) void bn1_kernel(const float* __restrict__ src,
                                                  const float* __restrict__ gamma,
                                                  const float* __restrict__ beta)
{
    __shared__ float vals[NROW];
    __shared__ float red[8];
    const int d = blockIdx.x, line = blockIdx.y, tid = threadIdx.x;
    float s = 0.f, ss = 0.f;
    for (int idx = tid; idx < NROW; idx += 256) {
        size_t off = (size_t)idx * DQ + d;
        float v;
        if (line == 0)      v = src[off];
        else if (line == 1) v = src[off] + g_attn[off];
        else                v = g_attn[off];
        vals[idx] = v; s += v; ss += v*v;
    }
    s  = blockSum(s,  red, 8);
    ss = blockSum(ss, red, 8);
    float mu  = s * (1.f/NROW);
    float var = ss * (1.f/NROW) - mu*mu;
    float scale = gamma[line*DQ + d] * rsqrtf(var + 1e-5f);
    float shift = beta [line*DQ + d] - mu*scale;
    float* dst = g_lines + (size_t)line * NROW * DQ;
    for (int idx = tid; idx < NROW; idx += 256) {
        int bb = idx >> 9, ll = idx & 511;
        dst[(size_t)(ll*8 + bb)*DQ + d] = vals[idx]*scale + shift;
    }
}

// ---- GEMM (64x64 tile, 256 threads) ----
__global__ __launch_bounds__(256) void gemm_kernel(const float* __restrict__ W,
                                                   const float* __restrict__ bias1,
                                                   const float* __restrict__ bias2,
                                                   int K, int phase)
{
    __shared__ float As[16][68];
    __shared__ float Bs[16][68];
    const int stack = blockIdx.z;
    const float* Ab = (phase ? g_h0 : g_lines) + (size_t)stack * NROW * K;
    const float* Wb = W + (size_t)stack * GDIM * K;
    const float* b1 = bias1 + stack * GDIM;
    const float* b2 = bias2 + stack * GDIM;
    float* Cb = g_xg + (size_t)stack * NROW * GDIM;
    const int m0 = blockIdx.x * 64, n0 = blockIdx.y * 64;
    const int tid = threadIdx.x;
    const int tm = tid & 15, tn = tid >> 4;
    const int li = tid >> 2, lj = tid & 3;
    float acc[4][4] = {};
    for (int k0 = 0; k0 < K; k0 += 16) {
        float4 av = *(const float4*)&Ab[(size_t)(m0+li)*K + k0 + lj*4];
        float4 wv = *(const float4*)&Wb[(size_t)(n0+li)*K + k0 + lj*4];
        As[lj*4+0][li] = av.x; As[lj*4+1][li] = av.y; As[lj*4+2][li] = av.z; As[lj*4+3][li] = av.w;
        Bs[lj*4+0][li] = wv.x; Bs[lj*4+1][li] = wv.y; Bs[lj*4+2][li] = wv.z; Bs[lj*4+3][li] = wv.w;
        __syncthreads();
        #pragma unroll
        for (int kk = 0; kk < 16; kk++) {
            float4 a  = *(const float4*)&As[kk][tm*4];
            float4 w4 = *(const float4*)&Bs[kk][tn*4];
            float ar[4] = {a.x, a.y, a.z, a.w};
            float wr[4] = {w4.x, w4.y, w4.z, w4.w};
            #pragma unroll
            for (int i2 = 0; i2 < 4; i2++)
                #pragma unroll
                for (int j2 = 0; j2 < 4; j2++)
                    acc[i2][j2] = fmaf(ar[i2], wr[j2], acc[i2][j2]);
        }
        __syncthreads();
    }
    #pragma unroll
    for (int j2 = 0; j2 < 4; j2++) {
        int n = n0 + tn*4 + j2;
        float bsum = b1[n] + b2[n];
        #pragma unroll
        for (int i2 = 0; i2 < 4; i2++) {
            int m = m0 + tm*4 + i2;
            Cb[(size_t)m*GDIM + n] = acc[i2][j2] + bsum;
        }
    }
}

// ---- LSTM: cluster of 8 CTAs; paired-b64 DSMEM h-broadcast + split HW barrier ----
#define SEG 68
__global__ __launch_bounds__(512, 1) void lstm_kernel(const float* __restrict__ Whh,
                                                      int phase)
{
    const int ug = blockIdx.x, bg = blockIdx.y, stack = blockIdx.z;
    const int tid = threadIdx.x;
    const int r = tid >> 2, kq = tid & 3;
    const int gi = r >> 5, u = r & 31;
    const int j0 = ug * 32;

    __shared__ __align__(16) float hs[2][2][4*SEG];   // [parity][batch][seg]
    __shared__ float sgate[128][2];

    ull wp[32];
    {
        const float* wrow = Whh + ((size_t)stack << 18)
                          + ((size_t)(gi*256 + j0 + u) << 8) + kq*64;
        #pragma unroll
        for (int i = 0; i < 32; i++) wp[i] = pack2(wrow[2*i], wrow[2*i+1]);
    }
    for (int i = tid; i < 2*2*4*SEG; i += 512) ((float*)hs)[i] = 0.f;

    const float* xg_s = g_xg + (size_t)stack * NROW * GDIM;
    float* hseq_s = (phase ? g_h1 : g_h0) + (size_t)stack * NROW * HQ;

    const int au = tid >> 1, ab = tid & 1;
    const int bglob = bg*2 + ab;
    float c_state = 0.f;

    float xr0 = 0.f, xr1 = 0.f, xr2 = 0.f, xr3 = 0.f;
    if (tid < 64) {
        const float* xp = xg_s + (size_t)(0*8 + bglob)*GDIM + j0 + au;
        xr0 = xp[0]; xr1 = xp[256]; xr2 = xp[512]; xr3 = xp[768];
    }
    asm volatile("barrier.cluster.arrive.aligned;" ::: "memory");
    asm volatile("barrier.cluster.wait.aligned;" ::: "memory");

    for (int t = 0; t < LQ; t++) {
        const int par = t & 1;
        const ulonglong2* h0 = (const ulonglong2*)&hs[par][0][kq*SEG];
        const ulonglong2* h1 = (const ulonglong2*)&hs[par][1][kq*SEG];
        ull acc0 = pack2(0.f, 0.f), acc1 = pack2(0.f, 0.f);
        #pragma unroll
        for (int i = 0; i < 16; i++) {
            ulonglong2 v0 = h0[i], v1 = h1[i];
            ffma2(acc0, wp[2*i],   v0.x);
            ffma2(acc0, wp[2*i+1], v0.y);
            ffma2(acc1, wp[2*i],   v1.x);
            ffma2(acc1, wp[2*i+1], v1.y);
        }
        float d0 = pairsum(acc0), d1 = pairsum(acc1);
        d0 += __shfl_xor_sync(0xffffffffu, d0, 1);
        d1 += __shfl_xor_sync(0xffffffffu, d1, 1);
        d0 += __shfl_xor_sync(0xffffffffu, d0, 2);
        d1 += __shfl_xor_sync(0xffffffffu, d1, 2);
        if (kq == 0) { sgate[r][0] = d0; sgate[r][1] = d1; }
        __syncthreads();   // all hs[par] reads complete before any arrive below

        float hreg = 0.f;
        if (tid < 64) {
            float pi = sgate[ 0 + au][ab] + xr0;
            float pf = sgate[32 + au][ab] + xr1;
            float pg = sgate[64 + au][ab] + xr2;
            float po = sgate[96 + au][ab] + xr3;
            float ig = sigmoid_t(pi);
            float fg = sigmoid_t(pf);
            float gg = tanh_fast(pg);
            float og = sigmoid_t(po);
            float c  = fg * c_state + ig * gg;
            c_state = c;
            hreg = og * tanh_fast(c);
            // pair adjacent-k producers: tid and tid^2 (same batch ab, k and k+1)
            float hnb = __shfl_xor_sync(0xffffffffu, hreg, 2);
            if ((au & 1) == 0) {
                const int k = j0 + au;          // even
                ull hv2 = pack2(hreg, hnb);     // {h_k, h_{k+1}}
                uint32_t laddr = smem_u32(&hs[par^1][ab][(k >> 6)*SEG + (k & 63)]);
                #pragma unroll
                for (int tgt = 0; tgt < 8; tgt++) {
                    uint32_t raddr;
                    asm volatile("mapa.shared::cluster.u32 %0, %1, %2;"
                                 : "=r"(raddr) : "r"(laddr), "r"(tgt));
                    asm volatile("st.shared::cluster.b64 [%0], %1;"
                                 :: "r"(raddr), "l"(hv2) : "memory");
                }
            }
        }
        // arrive (release: publishes producers' remote stores) — UNCONDITIONAL
        asm volatile("barrier.cluster.arrive.aligned;" ::: "memory");
        // overlap gmem traffic with barrier latency
        if (tid < 64) {
            hseq_s[(size_t)(t*8 + bglob)*HQ + (j0 + au)] = hreg;
            if (t + 1 < LQ) {
                const float* xp = xg_s + (size_t)((t+1)*8 + bglob)*GDIM + j0 + au;
                xr0 = xp[0]; xr1 = xp[256]; xr2 = xp[512]; xr3 = xp[768];
            }
        }
        asm volatile("barrier.cluster.wait.aligned;" ::: "memory");
    }
}

__global__ __launch_bounds__(256) void bn2stats_kernel(const float* __restrict__ cat_w)
{
    const int h = threadIdx.x, blk = blockIdx.x;
    float s = 0.f, ss = 0.f;
    for (int tt = 0; tt < 16; tt++) {
        int t = blk*16 + tt;
        float w0 = cat_w[(size_t)(0*LQ + t)*HQ + h];
        float w1 = cat_w[(size_t)(1*LQ + t)*HQ + h];
        float w2 = cat_w[(size_t)(2*LQ + t)*HQ + h];
        float inv = 1.f/(w0 + w1 + w2);
        w0 *= inv; w1 *= inv; w2 *= inv;
        #pragma unroll
        for (int b = 0; b < 8; b++) {
            size_t row = (size_t)(t*8 + b)*HQ + h;
            float v = g_h1[row]*w0 + g_h1[row + (size_t)NROW*HQ]*w1
                    + g_h1[row + 2*(size_t)NROW*HQ]*w2;
            s += v; ss += v*v;
        }
    }
    g_part[(blk*2 + 0)*HQ + h] = s;
    g_part[(blk*2 + 1)*HQ + h] = ss;
}

__global__ __launch_bounds__(256) void final_kernel(const float* __restrict__ cat_w,
                                                    const float* __restrict__ g2,
                                                    const float* __restrict__ b2,
                                                    const float* __restrict__ fcW,
                                                    const float* __restrict__ fcb,
                                                    float* __restrict__ out)
{
    __shared__ float catn[HQ][BQ];
    const int tid = threadIdx.x;
    float s = 0.f, ss = 0.f;
    for (int blk = 0; blk < 32; blk++) {
        s  += g_part[(blk*2 + 0)*HQ + tid];
        ss += g_part[(blk*2 + 1)*HQ + tid];
    }
    float mu  = s * (1.f/NROW);
    float var = ss * (1.f/NROW) - mu*mu;
    float scale = g2[tid] * rsqrtf(var + 1e-5f);
    float shift = b2[tid] - mu*scale;

    const int t = LQ - 1;
    float w0 = cat_w[(size_t)(0*LQ + t)*HQ + tid];
    float w1 = cat_w[(size_t)(1*LQ + t)*HQ + tid];
    float w2 = cat_w[(size_t)(2*LQ + t)*HQ + tid];
    float inv = 1.f/(w0 + w1 + w2);
    w0 *= inv; w1 *= inv; w2 *= inv;
    #pragma unroll
    for (int b = 0; b < 8; b++) {
        size_t row = (size_t)(t*8 + b)*HQ + tid;
        float v = g_h1[row]*w0 + g_h1[row + (size_t)NROW*HQ]*w1
                + g_h1[row + 2*(size_t)NROW*HQ]*w2;
        catn[tid][b] = v*scale + shift;
    }
    __syncthreads();
    if (tid < 64) {
        int b = tid >> 3, c = tid & 7;
        float acc = fcb[c];
        for (int hh = 0; hh < HQ; hh++) acc = fmaf(catn[hh][b], fcW[c*HQ + hh], acc);
        out[b*8 + c] = acc;
    }
}

static void launch_lstm(const float* Whh, int phase, cudaStream_t st = 0)
{
    cudaLaunchConfig_t cfg = {};
    cfg.gridDim  = dim3(8, 4, 3);
    cfg.blockDim = dim3(512, 1, 1);
    cfg.dynamicSmemBytes = 0;
    cfg.stream = st;
    cudaLaunchAttribute attrs[1];
    attrs[0].id = cudaLaunchAttributeClusterDimension;
    attrs[0].val.clusterDim = {8, 1, 1};
    cfg.attrs = attrs;
    cfg.numAttrs = 1;
    cudaLaunchKernelEx(&cfg, lstm_kernel, Whh, phase);
}

extern "C" void kernel_launch(void* const* d_in, const int* in_sizes, int n_in,
                              void* d_out, int out_size)
{
    const float* src    = (const float*)d_in[0];
    const float* attn_w = (const float*)d_in[1];
    const float* cat_w  = (const float*)d_in[2];
    const float* bn1_g  = (const float*)d_in[3];
    const float* bn1_b  = (const float*)d_in[4];
    const float* bn2_g  = (const float*)d_in[5];
    const float* bn2_b  = (const float*)d_in[6];
    const float* Wih0   = (const float*)d_in[7];
    const float* Whh0   = (const float*)d_in[8];
    const float* bih0   = (const float*)d_in[9];
    const float* bhh0   = (const float*)d_in[10];
    const float* Wih1   = (const float*)d_in[11];
    const float* Whh1   = (const float*)d_in[12];
    const float* bih1   = (const float*)d_in[13];
    const float* bhh1   = (const float*)d_in[14];
    const float* fcW    = (const float*)d_in[15];
    const float* fcb    = (const float*)d_in[16];
    float* out = (float*)d_out;

    attn_kernel<<<dim3(LQ, BQ), 128>>>(src, attn_w);                  // 0
    bn1_kernel<<<dim3(DQ, 3), 256>>>(src, bn1_g, bn1_b);              // 1
    gemm_kernel<<<dim3(64, 16, 3), 256>>>(Wih0, bih0, bhh0, 64, 0);   // 2
    launch_lstm(Whh0, 0);                                             // 3
    gemm_kernel<<<dim3(64, 16, 3), 256>>>(Wih1, bih1, bhh1, 256, 1);  // 4
    launch_lstm(Whh1, 1);                                             // 5  <- ncu capture slot
    bn2stats_kernel<<<32, 256>>>(cat_w);                              // 6
    final_kernel<<<1, 256>>>(cat_w, bn2_g, bn2_b, fcW, fcb, out);     // 7
}

// round 16
// speedup vs baseline: 1.4983x; 1.2936x over previous
#include <cuda_runtime.h>
#include <stdint.h>

#define LQ 512
#define BQ 8
#define DQ 64
#define HQ 256
#define NROW 4096
#define GDIM 1024

typedef unsigned long long ull;

__device__ float g_attn [BQ*LQ*DQ];
__device__ float g_lines[3*NROW*DQ];
__device__ float g_xg   [3*NROW*GDIM];
__device__ float g_h0   [3*NROW*HQ];
__device__ float g_h1   [3*NROW*HQ];
__device__ float g_part [32*2*HQ];

static __device__ __forceinline__ float tanh_fast(float x) {
    float y; asm("tanh.approx.f32 %0, %1;" : "=f"(y) : "f"(x)); return y;
}
static __device__ __forceinline__ float sigmoid_t(float x) {
    return fmaf(0.5f, tanh_fast(0.5f*x), 0.5f);
}
static __device__ __forceinline__ ull pack2(float lo, float hi) {
    ull r; asm("mov.b64 %0, {%1, %2};" : "=l"(r) : "f"(lo), "f"(hi)); return r;
}
static __device__ __forceinline__ void ffma2(ull& acc, ull w, ull h) {
    asm("fma.rn.f32x2 %0, %1, %2, %0;" : "+l"(acc) : "l"(w), "l"(h));
}
static __device__ __forceinline__ ull addp2(ull a, ull b) {
    ull r; asm("add.rn.f32x2 %0, %1, %2;" : "=l"(r) : "l"(a), "l"(b)); return r;
}
static __device__ __forceinline__ float pairsum(ull v) {
    float lo, hi; asm("mov.b64 {%0, %1}, %2;" : "=f"(lo), "=f"(hi) : "l"(v));
    return lo + hi;
}
static __device__ __forceinline__ uint32_t smem_u32(const void* p) {
    uint32_t a;
    asm("{ .reg .u64 t; cvta.to.shared.u64 t, %1; cvt.u32.u64 %0, t; }" : "=r"(a) : "l"(p));
    return a;
}
static __device__ __forceinline__ float blockSum(float v, float* red, int nw) {
    #pragma unroll
    for (int o = 16; o; o >>= 1) v += __shfl_xor_sync(0xffffffffu, v, o);
    if ((threadIdx.x & 31) == 0) red[threadIdx.x >> 5] = v;
    __syncthreads();
    float r = red[0];
    for (int i = 1; i < nw; i++) r += red[i];
    __syncthreads();
    return r;
}
static __device__ __forceinline__ float blockMax(float v, float* red, int nw) {
    #pragma unroll
    for (int o = 16; o; o >>= 1) v = fmaxf(v, __shfl_xor_sync(0xffffffffu, v, o));
    if ((threadIdx.x & 31) == 0) red[threadIdx.x >> 5] = v;
    __syncthreads();
    float r = red[0];
    for (int i = 1; i < nw; i++) r = fmaxf(r, red[i]);
    __syncthreads();
    return r;
}

__global__ __launch_bounds__(128) void attn_kernel(const float* __restrict__ x,
                                                   const float* __restrict__ attn_w)
{
    __shared__ float xl[DQ];
    __shared__ float s1[LQ], s2[LQ], p1[LQ], p2[LQ];
    __shared__ float red[4];
    __shared__ float comb[3][DQ];
    const int l = blockIdx.x, b = blockIdx.y, tid = threadIdx.x;
    const float* xb = x + (size_t)b * LQ * DQ;

    if (tid < DQ) xl[tid] = xb[(size_t)l * DQ + tid];
    __syncthreads();

    for (int m = tid; m <= l; m += 128) {
        const float4* row = (const float4*)(xb + (size_t)m * DQ);
        float dot = 0.f, ts = 0.f;
        #pragma unroll
        for (int q = 0; q < 16; q++) {
            float4 v = row[q];
            float a0 = xl[4*q+0], a1 = xl[4*q+1], a2 = xl[4*q+2], a3 = xl[4*q+3];
            dot += a0*v.x + a1*v.y + a2*v.z + a3*v.w;
            ts  += tanh_fast(a0+v.x) + tanh_fast(a1+v.y)
                 + tanh_fast(a2+v.z) + tanh_fast(a3+v.w);
        }
        s1[m] = dot; s2[m] = ts;
    }
    __syncthreads();

    float m1 = -1e30f, m3 = -1e30f;
    for (int m = tid; m <= l; m += 128) { m1 = fmaxf(m1, s1[m]); m3 = fmaxf(m3, s2[m]); }
    m1 = blockMax(m1, red, 4);
    m3 = blockMax(m3, red, 4);
    float m2 = m1 * 0.125f;

    float z1 = 0.f, z2 = 0.f, z3 = 0.f;
    for (int m = tid; m <= l; m += 128) {
        float e1 = __expf(s1[m] - m1);
        float e2 = __expf(s1[m]*0.125f - m2);
        float e3 = __expf(s2[m] - m3);
        p1[m] = e1; p2[m] = e2; s2[m] = e3;
        z1 += e1; z2 += e2; z3 += e3;
    }
    z1 = blockSum(z1, red, 4);
    z2 = blockSum(z2, red, 4);
    z3 = blockSum(z3, red, 4);
    const float i1 = 1.f/z1, i2 = 1.f/z2, i3 = 1.f/z3;

    const int d = tid & 63, half = tid >> 6;
    float aP = 0.f, aS = 0.f, aA = 0.f;
    for (int m = half; m <= l; m += 2) {
        float xv = xb[(size_t)m * DQ + d];
        aP += p1[m]*xv; aS += p2[m]*xv; aA += s2[m]*xv;
    }
    if (half) { comb[0][d] = aP; comb[1][d] = aS; comb[2][d] = aA; }
    __syncthreads();
    if (!half) {
        aP = (aP + comb[0][d]) * i1;
        aS = (aS + comb[1][d]) * i2;
        aA = (aA + comb[2][d]) * i3;
        float w0 = attn_w[(size_t)(0*LQ + l)*DQ + d];
        float w1 = attn_w[(size_t)(1*LQ + l)*DQ + d];
        float w2 = attn_w[(size_t)(2*LQ + l)*DQ + d];
        float inv = 1.f/(w0 + w1 + w2);
        g_attn[((size_t)b*LQ + l)*DQ + d] = (aP*w0 + aA*w1 + aS*w2)*inv;
    }
}

__global__ __launch_bounds__(256) void bn1_kernel(const float* __restrict__ src,
                                                  const float* __restrict__ gamma,
                                                  const float* __restrict__ beta)
{
    __shared__ float vals[NROW];
    __shared__ float red[8];
    const int d = blockIdx.x, line = blockIdx.y, tid = threadIdx.x;
    float s = 0.f, ss = 0.f;
    for (int idx = tid; idx < NROW; idx += 256) {
        size_t off = (size_t)idx * DQ + d;
        float v;
        if (line == 0)      v = src[off];
        else if (line == 1) v = src[off] + g_attn[off];
        else                v = g_attn[off];
        vals[idx] = v; s += v; ss += v*v;
    }
    s  = blockSum(s,  red, 8);
    ss = blockSum(ss, red, 8);
    float mu  = s * (1.f/NROW);
    float var = ss * (1.f/NROW) - mu*mu;
    float scale = gamma[line*DQ + d] * rsqrtf(var + 1e-5f);
    float shift = beta [line*DQ + d] - mu*scale;
    float* dst = g_lines + (size_t)line * NROW * DQ;
    for (int idx = tid; idx < NROW; idx += 256) {
        int bb = idx >> 9, ll = idx & 511;
        dst[(size_t)(ll*8 + bb)*DQ + d] = vals[idx]*scale + shift;
    }
}

// ---- GEMM (64x64 tile, 256 threads) ----
__global__ __launch_bounds__(256) void gemm_kernel(const float* __restrict__ W,
                                                   const float* __restrict__ bias1,
                                                   const float* __restrict__ bias2,
                                                   int K, int phase)
{
    __shared__ float As[16][68];
    __shared__ float Bs[16][68];
    const int stack = blockIdx.z;
    const float* Ab = (phase ? g_h0 : g_lines) + (size_t)stack * NROW * K;
    const float* Wb = W + (size_t)stack * GDIM * K;
    const float* b1 = bias1 + stack * GDIM;
    const float* b2 = bias2 + stack * GDIM;
    float* Cb = g_xg + (size_t)stack * NROW * GDIM;
    const int m0 = blockIdx.x * 64, n0 = blockIdx.y * 64;
    const int tid = threadIdx.x;
    const int tm = tid & 15, tn = tid >> 4;
    const int li = tid >> 2, lj = tid & 3;
    float acc[4][4] = {};
    for (int k0 = 0; k0 < K; k0 += 16) {
        float4 av = *(const float4*)&Ab[(size_t)(m0+li)*K + k0 + lj*4];
        float4 wv = *(const float4*)&Wb[(size_t)(n0+li)*K + k0 + lj*4];
        As[lj*4+0][li] = av.x; As[lj*4+1][li] = av.y; As[lj*4+2][li] = av.z; As[lj*4+3][li] = av.w;
        Bs[lj*4+0][li] = wv.x; Bs[lj*4+1][li] = wv.y; Bs[lj*4+2][li] = wv.z; Bs[lj*4+3][li] = wv.w;
        __syncthreads();
        #pragma unroll
        for (int kk = 0; kk < 16; kk++) {
            float4 a  = *(const float4*)&As[kk][tm*4];
            float4 w4 = *(const float4*)&Bs[kk][tn*4];
            float ar[4] = {a.x, a.y, a.z, a.w};
            float wr[4] = {w4.x, w4.y, w4.z, w4.w};
            #pragma unroll
            for (int i2 = 0; i2 < 4; i2++)
                #pragma unroll
                for (int j2 = 0; j2 < 4; j2++)
                    acc[i2][j2] = fmaf(ar[i2], wr[j2], acc[i2][j2]);
        }
        __syncthreads();
    }
    #pragma unroll
    for (int j2 = 0; j2 < 4; j2++) {
        int n = n0 + tn*4 + j2;
        float bsum = b1[n] + b2[n];
        #pragma unroll
        for (int i2 = 0; i2 < 4; i2++) {
            int m = m0 + tm*4 + i2;
            Cb[(size_t)m*GDIM + n] = acc[i2][j2] + bsum;
        }
    }
}

// ---- LSTM: cluster of 8 CTAs; 8-rows-per-thread matvec (h-reuse) + split HW barrier ----
// h layout: hsx[par][b][k + (k>>5)*4]  (16B pad per 128B -> conflict-free LDS.128)
#define HPAD 288
__global__ __launch_bounds__(512, 1) void lstm_kernel(const float* __restrict__ Whh,
                                                      int phase)
{
    const int ug = blockIdx.x, bg = blockIdx.y, stack = blockIdx.z;
    const int tid = threadIdx.x;
    const int w = tid >> 5, lane = tid & 31;
    const int j0 = ug * 32;

    __shared__ __align__(16) float hsx[2][2][HPAD];
    __shared__ float sgate[128][2];

    // warp w owns rows w*8..w*8+7; lane owns k in [lane*8, lane*8+8)
    // wp[r][q] = packed {W[row][lane*8+2q], W[row][lane*8+2q+1]}
    ull wp[8][4];
    #pragma unroll
    for (int rl = 0; rl < 8; rl++) {
        int rr = w*8 + rl;
        int rglob = ((rr >> 5) << 8) + j0 + (rr & 31);    // gate*256 + j0 + unit
        const float* wrow = Whh + ((size_t)stack << 18) + ((size_t)rglob << 8) + lane*8;
        #pragma unroll
        for (int q = 0; q < 4; q++) wp[rl][q] = pack2(wrow[2*q], wrow[2*q+1]);
    }
    for (int i = tid; i < 2*2*HPAD; i += 512) ((float*)hsx)[i] = 0.f;

    const float* xg_s = g_xg + (size_t)stack * NROW * GDIM;
    float* hseq_s = (phase ? g_h1 : g_h0) + (size_t)stack * NROW * HQ;

    const int au = tid >> 1, ab = tid & 1;
    const int bglob = bg*2 + ab;
    float c_state = 0.f;

    float xr0 = 0.f, xr1 = 0.f, xr2 = 0.f, xr3 = 0.f;
    if (tid < 64) {
        const float* xp = xg_s + (size_t)(0*8 + bglob)*GDIM + j0 + au;
        xr0 = xp[0]; xr1 = xp[256]; xr2 = xp[512]; xr3 = xp[768];
    }
    asm volatile("barrier.cluster.arrive.aligned;" ::: "memory");
    asm volatile("barrier.cluster.wait.aligned;" ::: "memory");

    const int hbase = lane*8 + (lane >> 2)*4;   // padded float index of k=lane*8

    for (int t = 0; t < LQ; t++) {
        const int par = t & 1;
        float a[16];   // a[r*2+b]
        #pragma unroll
        for (int b = 0; b < 2; b++) {
            ulonglong2 hA = *(const ulonglong2*)&hsx[par][b][hbase];
            ulonglong2 hB = *(const ulonglong2*)&hsx[par][b][hbase + 4];
            ull hq0 = hA.x, hq1 = hA.y, hq2 = hB.x, hq3 = hB.y;
            #pragma unroll
            for (int rl = 0; rl < 8; rl++) {
                ull e = pack2(0.f, 0.f), f = pack2(0.f, 0.f);
                ffma2(e, wp[rl][0], hq0);
                ffma2(f, wp[rl][1], hq1);
                ffma2(e, wp[rl][2], hq2);
                ffma2(f, wp[rl][3], hq3);
                a[rl*2 + b] = pairsum(addp2(e, f));
            }
        }
        // pairwise-merge butterfly: 16 values over 32 lanes
        #pragma unroll
        for (int bit = 16, vals = 16; bit >= 2; bit >>= 1, vals >>= 1) {
            const int half = vals >> 1;
            const bool up = (lane & bit) != 0;
            #pragma unroll
            for (int i = 0; i < 8; i++) {
                if (i < half) {
                    float send = up ? a[i] : a[i + half];
                    float keep = up ? a[i + half] : a[i];
                    float recv = __shfl_xor_sync(0xffffffffu, send, bit);
                    a[i] = keep + recv;
                }
            }
        }
        a[0] += __shfl_xor_sync(0xffffffffu, a[0], 1);
        // lane l holds value v=(l>>1)&15: r_local=(l>>2)&7, b=(l>>1)&1
        if ((lane & 1) == 0)
            sgate[w*8 + ((lane >> 2) & 7)][(lane >> 1) & 1] = a[0];
        __syncthreads();   // all hsx[par] reads complete before any arrive below

        float hreg = 0.f;
        if (tid < 64) {
            float pi = sgate[ 0 + au][ab] + xr0;
            float pf = sgate[32 + au][ab] + xr1;
            float pg = sgate[64 + au][ab] + xr2;
            float po = sgate[96 + au][ab] + xr3;
            float ig = sigmoid_t(pi);
            float fg = sigmoid_t(pf);
            float gg = tanh_fast(pg);
            float og = sigmoid_t(po);
            float c  = fg * c_state + ig * gg;
            c_state = c;
            hreg = og * tanh_fast(c);
            // pair adjacent-k producers: tid and tid^2 (same batch ab, k and k+1)
            float hnb = __shfl_xor_sync(0xffffffffu, hreg, 2);
            if ((au & 1) == 0) {
                const int k = j0 + au;                 // even
                const int fidx = k + (k >> 5)*4;       // padded index (k,k+1 adjacent)
                ull hv2 = pack2(hreg, hnb);
                uint32_t laddr = smem_u32(&hsx[par^1][ab][fidx]);
                #pragma unroll
                for (int tgt = 0; tgt < 8; tgt++) {
                    uint32_t raddr;
                    asm volatile("mapa.shared::cluster.u32 %0, %1, %2;"
                                 : "=r"(raddr) : "r"(laddr), "r"(tgt));
                    asm volatile("st.shared::cluster.b64 [%0], %1;"
                                 :: "r"(raddr), "l"(hv2) : "memory");
                }
            }
        }
        // arrive (release: publishes producers' remote stores) — UNCONDITIONAL
        asm volatile("barrier.cluster.arrive.aligned;" ::: "memory");
        if (tid < 64) {
            hseq_s[(size_t)(t*8 + bglob)*HQ + (j0 + au)] = hreg;
            if (t + 1 < LQ) {
                const float* xp = xg_s + (size_t)((t+1)*8 + bglob)*GDIM + j0 + au;
                xr0 = xp[0]; xr1 = xp[256]; xr2 = xp[512]; xr3 = xp[768];
            }
        }
        asm volatile("barrier.cluster.wait.aligned;" ::: "memory");
    }
}

__global__ __launch_bounds__(256) void bn2stats_kernel(const float* __restrict__ cat_w)
{
    const int h = threadIdx.x, blk = blockIdx.x;
    float s = 0.f, ss = 0.f;
    for (int tt = 0; tt < 16; tt++) {
        int t = blk*16 + tt;
        float w0 = cat_w[(size_t)(0*LQ + t)*HQ + h];
        float w1 = cat_w[(size_t)(1*LQ + t)*HQ + h];
        float w2 = cat_w[(size_t)(2*LQ + t)*HQ + h];
        float inv = 1.f/(w0 + w1 + w2);
        w0 *= inv; w1 *= inv; w2 *= inv;
        #pragma unroll
        for (int b = 0; b < 8; b++) {
            size_t row = (size_t)(t*8 + b)*HQ + h;
            float v = g_h1[row]*w0 + g_h1[row + (size_t)NROW*HQ]*w1
                    + g_h1[row + 2*(size_t)NROW*HQ]*w2;
            s += v; ss += v*v;
        }
    }
    g_part[(blk*2 + 0)*HQ + h] = s;
    g_part[(blk*2 + 1)*HQ + h] = ss;
}

__global__ __launch_bounds__(256) void final_kernel(const float* __restrict__ cat_w,
                                                    const float* __restrict__ g2,
                                                    const float* __restrict__ b2,
                                                    const float* __restrict__ fcW,
                                                    const float* __restrict__ fcb,
                                                    float* __restrict__ out)
{
    __shared__ float catn[HQ][BQ];
    const int tid = threadIdx.x;
    float s = 0.f, ss = 0.f;
    for (int blk = 0; blk < 32; blk++) {
        s  += g_part[(blk*2 + 0)*HQ + tid];
        ss += g_part[(blk*2 + 1)*HQ + tid];
    }
    float mu  = s * (1.f/NROW);
    float var = ss * (1.f/NROW) - mu*mu;
    float scale = g2[tid] * rsqrtf(var + 1e-5f);
    float shift = b2[tid] - mu*scale;

    const int t = LQ - 1;
    float w0 = cat_w[(size_t)(0*LQ + t)*HQ + tid];
    float w1 = cat_w[(size_t)(1*LQ + t)*HQ + tid];
    float w2 = cat_w[(size_t)(2*LQ + t)*HQ + tid];
    float inv = 1.f/(w0 + w1 + w2);
    w0 *= inv; w1 *= inv; w2 *= inv;
    #pragma unroll
    for (int b = 0; b < 8; b++) {
        size_t row = (size_t)(t*8 + b)*HQ + tid;
        float v = g_h1[row]*w0 + g_h1[row + (size_t)NROW*HQ]*w1
                + g_h1[row + 2*(size_t)NROW*HQ]*w2;
        catn[tid][b] = v*scale + shift;
    }
    __syncthreads();
    if (tid < 64) {
        int b = tid >> 3, c = tid & 7;
        float acc = fcb[c];
        for (int hh = 0; hh < HQ; hh++) acc = fmaf(catn[hh][b], fcW[c*HQ + hh], acc);
        out[b*8 + c] = acc;
    }
}

static void launch_lstm(const float* Whh, int phase, cudaStream_t st = 0)
{
    cudaLaunchConfig_t cfg = {};
    cfg.gridDim  = dim3(8, 4, 3);
    cfg.blockDim = dim3(512, 1, 1);
    cfg.dynamicSmemBytes = 0;
    cfg.stream = st;
    cudaLaunchAttribute attrs[1];
    attrs[0].id = cudaLaunchAttributeClusterDimension;
    attrs[0].val.clusterDim = {8, 1, 1};
    cfg.attrs = attrs;
    cfg.numAttrs = 1;
    cudaLaunchKernelEx(&cfg, lstm_kernel, Whh, phase);
}

extern "C" void kernel_launch(void* const* d_in, const int* in_sizes, int n_in,
                              void* d_out, int out_size)
{
    const float* src    = (const float*)d_in[0];
    const float* attn_w = (const float*)d_in[1];
    const float* cat_w  = (const float*)d_in[2];
    const float* bn1_g  = (const float*)d_in[3];
    const float* bn1_b  = (const float*)d_in[4];
    const float* bn2_g  = (const float*)d_in[5];
    const float* bn2_b  = (const float*)d_in[6];
    const float* Wih0   = (const float*)d_in[7];
    const float* Whh0   = (const float*)d_in[8];
    const float* bih0   = (const float*)d_in[9];
    const float* bhh0   = (const float*)d_in[10];
    const float* Wih1   = (const float*)d_in[11];
    const float* Whh1   = (const float*)d_in[12];
    const float* bih1   = (const float*)d_in[13];
    const float* bhh1   = (const float*)d_in[14];
    const float* fcW    = (const float*)d_in[15];
    const float* fcb    = (const float*)d_in[16];
    float* out = (float*)d_out;

    attn_kernel<<<dim3(LQ, BQ), 128>>>(src, attn_w);                  // 0
    bn1_kernel<<<dim3(DQ, 3), 256>>>(src, bn1_g, bn1_b);              // 1
    gemm_kernel<<<dim3(64, 16, 3), 256>>>(Wih0, bih0, bhh0, 64, 0);   // 2
    launch_lstm(Whh0, 0);                                             // 3
    gemm_kernel<<<dim3(64, 16, 3), 256>>>(Wih1, bih1, bhh1, 256, 1);  // 4
    launch_lstm(Whh1, 1);                                             // 5  <- ncu capture slot
    bn2stats_kernel<<<32, 256>>>(cat_w);                              // 6
    final_kernel<<<1, 256>>>(cat_w, bn2_g, bn2_b, fcW, fcb, out);     // 7
}